// round 6
// baseline (speedup 1.0000x reference)
#include <cuda_runtime.h>
#include <cstdint>
#include <math.h>

#define BB   16
#define CC   512
#define HWW  1024
#define ABUF ((size_t)BB*CC*HWW)      // 8M floats = 32MB

// Scratch (__device__ globals; no allocs allowed)
__device__ float g_hxT[ABUF];   // normalized x, [b][hw][c]; reused as O after k,v
__device__ float g_hyT[ABUF];   // normalized y, [b][hw][c]
__device__ float g_qT [ABUF];   // [b][hw][c]
__device__ float g_kT [ABUF];   // [b][hw][c]
__device__ float g_vT [ABUF];   // [b][hw][c]
__device__ float g_v2 [ABUF];   // [b][c][hw]
__device__ float g_s  [(size_t)BB*HWW*HWW];  // 64MB scores

__device__ __forceinline__ uint32_t smem_u32(const void* p) {
    uint32_t a;
    asm("{ .reg .u64 t; cvta.to.shared.u64 t, %1; cvt.u32.u64 %0, t; }" : "=r"(a) : "l"(p));
    return a;
}
#define CP_ASYNC16(sa, ga) \
    asm volatile("cp.async.cg.shared.global [%0], [%1], 16;" :: "r"(sa), "l"(ga) : "memory")
#define CP_COMMIT() asm volatile("cp.async.commit_group;" ::: "memory")
#define CP_WAIT2()  asm volatile("cp.async.wait_group 2;" ::: "memory")

// ---------------------------------------------------------------------------
// tf32 mma.sync GEMM: D[m,n] = sum_k A[m,k]*B[n,k]; 128x128 block tile,
// 4-stage cp.async multistage pipeline, K-chunk 16, one barrier per chunk.
// 8 warps (2x4), warp tile 64x32 = 4x4 m16n8k8 MMAs.
// Smem [128][20] per tile: fragment LDS banks (20g+tg)%32 all-distinct.
// EPI: 0 = +bias[n] | 1 = *scale | 2 = none | 3 = +bias[m]+resid
// ---------------------------------------------------------------------------
template<int EPI>
__global__ __launch_bounds__(256, 2)
void mma_gemm(const float* __restrict__ A, const float* __restrict__ B,
              float* __restrict__ C, const float* __restrict__ bias,
              const float* __restrict__ resid,
              int NC, int lda, int ldb, int ldc,
              long aB, long bB, long cB, float scale)
{
    extern __shared__ float sm[];    // 4 stages x (A 128*20 + B 128*20)
    const int TP = 20, TILE = 128 * TP, STG = 2 * TILE;   // floats

    int t = threadIdx.x, lane = t & 31, w = t >> 5;
    int wr = w & 1, wc = w >> 1;          // warp grid 2 x 4
    int g = lane >> 2, tg = lane & 3;
    int bz = blockIdx.z, m0 = blockIdx.y * 128, n0 = blockIdx.x * 128;
    const float* Ab = A + (size_t)bz * aB;
    const float* Bb = B + (size_t)bz * bB;
    float*       Cb = C + (size_t)bz * cB;
    uint32_t smb = smem_u32(sm);

    // Per stage: A tile 128x16 + B tile 128x16; 512 16B-chunks per tile,
    // 256 threads -> 2 chunks per thread per tile.
    auto load = [&](int c, int s) {
        int k0 = c * 16;
        #pragma unroll
        for (int j = 0; j < 2; j++) {
            int idx = t + 256 * j;          // 0..511
            int r = idx >> 2, cq = (idx & 3) * 4;
            const float* ga = Ab + (size_t)(m0 + r) * lda + k0 + cq;
            const float* gb = Bb + (size_t)(n0 + r) * ldb + k0 + cq;
            uint32_t sa  = smb + (uint32_t)(s * STG + r * TP + cq) * 4u;
            uint32_t sbm = smb + (uint32_t)(s * STG + TILE + r * TP + cq) * 4u;
            CP_ASYNC16(sa, ga);
            CP_ASYNC16(sbm, gb);
        }
    };

    float acc[4][4][4];
    #pragma unroll
    for (int i = 0; i < 4; i++)
        #pragma unroll
        for (int j = 0; j < 4; j++)
            #pragma unroll
            for (int q = 0; q < 4; q++) acc[i][j][q] = 0.f;

    // Prologue: 3 stages in flight
    load(0, 0); CP_COMMIT();
    load(1, 1); CP_COMMIT();
    load(2, 2); CP_COMMIT();

    for (int c = 0; c < NC; c++) {
        CP_WAIT2();                        // stage c complete (<=2 newer pending)
        __syncthreads();                   // stage c visible to all warps
        // Issue next-stage loads first so they overlap this chunk's MMAs.
        // Overwrites slot (c-1)%4, consumed at iter c-1 (barrier above orders it).
        if (c + 3 < NC) { load(c + 3, (c + 3) & 3); CP_COMMIT(); }

        const float* As = sm + (c & 3) * STG;
        const float* Bs = As + TILE;
        #pragma unroll
        for (int kk = 0; kk < 16; kk += 8) {
            uint32_t af[4][4], bf[4][2];
            #pragma unroll
            for (int i = 0; i < 4; i++) {
                const float* ap = As + (size_t)(wr * 64 + i * 16 + g) * TP + kk + tg;
                af[i][0] = __float_as_uint(ap[0]);
                af[i][1] = __float_as_uint(ap[8 * TP]);
                af[i][2] = __float_as_uint(ap[4]);
                af[i][3] = __float_as_uint(ap[8 * TP + 4]);
            }
            #pragma unroll
            for (int j = 0; j < 4; j++) {
                const float* bp = Bs + (size_t)(wc * 32 + j * 8 + g) * TP + kk + tg;
                bf[j][0] = __float_as_uint(bp[0]);
                bf[j][1] = __float_as_uint(bp[4]);
            }
            #pragma unroll
            for (int i = 0; i < 4; i++)
                #pragma unroll
                for (int j = 0; j < 4; j++)
                    asm volatile(
                        "mma.sync.aligned.m16n8k8.row.col.f32.tf32.tf32.f32 "
                        "{%0,%1,%2,%3},{%4,%5,%6,%7},{%8,%9},{%0,%1,%2,%3};"
                        : "+f"(acc[i][j][0]), "+f"(acc[i][j][1]),
                          "+f"(acc[i][j][2]), "+f"(acc[i][j][3])
                        : "r"(af[i][0]), "r"(af[i][1]), "r"(af[i][2]), "r"(af[i][3]),
                          "r"(bf[j][0]), "r"(bf[j][1]));
        }
    }

    // Epilogue: acc[i][j] -> rows m0+wr*64+i*16+{g, g+8}, cols n0+wc*32+j*8+2*tg
    int mrow = m0 + wr * 64;
    int ncol = n0 + wc * 32;
    #pragma unroll
    for (int i = 0; i < 4; i++) {
        int r0 = mrow + i * 16 + g, r1 = r0 + 8;
        float bm0 = 0.f, bm1 = 0.f;
        if (EPI == 3) { bm0 = __ldg(&bias[r0]); bm1 = __ldg(&bias[r1]); }
        #pragma unroll
        for (int j = 0; j < 4; j++) {
            int cc = ncol + j * 8 + 2 * tg;
            float2 v0 = make_float2(acc[i][j][0], acc[i][j][1]);
            float2 v1 = make_float2(acc[i][j][2], acc[i][j][3]);
            if (EPI == 0) {
                float b0 = __ldg(&bias[cc]), b1 = __ldg(&bias[cc + 1]);
                v0.x += b0; v0.y += b1; v1.x += b0; v1.y += b1;
            } else if (EPI == 1) {
                v0.x *= scale; v0.y *= scale; v1.x *= scale; v1.y *= scale;
            } else if (EPI == 3) {
                const float* Rb = resid + (size_t)bz * cB;
                float2 x0 = *(const float2*)(Rb + (size_t)r0 * ldc + cc);
                float2 x1 = *(const float2*)(Rb + (size_t)r1 * ldc + cc);
                v0.x += bm0 + x0.x; v0.y += bm0 + x0.y;
                v1.x += bm1 + x1.x; v1.y += bm1 + x1.y;
            }
            *(float2*)(Cb + (size_t)r0 * ldc + cc) = v0;
            *(float2*)(Cb + (size_t)r1 * ldc + cc) = v1;
        }
    }
}

// ---------------------------------------------------------------------------
// GroupNorm with transposed output [b][hw][c]. One block per (b, group).
// ---------------------------------------------------------------------------
__global__ void gn_t_kernel(const float* __restrict__ x, const float* __restrict__ sc,
                            const float* __restrict__ bi, float* __restrict__ outT)
{
    extern __shared__ float xs[];      // 16 * 1026
    __shared__ float shs[8], shq[8], shm[2];
    int bg = blockIdx.x;
    int b = bg >> 5, g = bg & 31;
    const float* xp = x + ((size_t)b * CC + (size_t)g * 16) * HWW;
    int t = threadIdx.x;

    float s = 0.f, sq = 0.f;
    #pragma unroll 4
    for (int j = 0; j < 64; j++) {
        int idx = t + 256 * j;               // idx = c*1024 + hw
        float v = xp[idx];
        xs[(idx >> 10) * 1026 + (idx & 1023)] = v;
        s += v; sq += v * v;
    }
    #pragma unroll
    for (int o = 16; o > 0; o >>= 1) {
        s  += __shfl_xor_sync(0xffffffffu, s,  o);
        sq += __shfl_xor_sync(0xffffffffu, sq, o);
    }
    if ((t & 31) == 0) { shs[t >> 5] = s; shq[t >> 5] = sq; }
    __syncthreads();
    if (t == 0) {
        float S = 0.f, Q = 0.f;
        #pragma unroll
        for (int i = 0; i < 8; i++) { S += shs[i]; Q += shq[i]; }
        float mean = S * (1.f / 16384.f);
        float var  = Q * (1.f / 16384.f) - mean * mean;
        shm[0] = mean;
        shm[1] = rsqrtf(var + 1e-6f);
    }
    __syncthreads();
    float mean = shm[0], rs = shm[1];
    int cl = t & 15;
    float scv = __ldg(&sc[g * 16 + cl]) * rs;
    float biv = __ldg(&bi[g * 16 + cl]);
    float* op = outT + (size_t)b * HWW * CC + g * 16;
    #pragma unroll 4
    for (int j = 0; j < 64; j++) {
        int idx = t + 256 * j;
        int hw = idx >> 4;
        op[(size_t)hw * CC + cl] = (xs[cl * 1026 + hw] - mean) * scv + biv;
    }
}

// ---------------------------------------------------------------------------
// 32x32 tiled transpose: vT [b][hw][c] -> v2 [b][c][hw]
// ---------------------------------------------------------------------------
__global__ void transpose_kernel(const float* __restrict__ vT, float* __restrict__ v2)
{
    __shared__ float ts[32][33];
    int b = blockIdx.z;
    int hw0 = blockIdx.x * 32, c0 = blockIdx.y * 32;
    const float* src = vT + (size_t)b * CC * HWW;
    float*       dst = v2 + (size_t)b * CC * HWW;
    int t = threadIdx.x, tx = t & 31, ty = t >> 5;
    #pragma unroll
    for (int i = 0; i < 4; i++) {
        int hw = hw0 + ty + i * 8;
        ts[ty + i * 8][tx] = src[(size_t)hw * CC + c0 + tx];
    }
    __syncthreads();
    #pragma unroll
    for (int i = 0; i < 4; i++) {
        int c = c0 + ty + i * 8;
        dst[(size_t)c * HWW + hw0 + tx] = ts[tx][ty + i * 8];
    }
}

// ---------------------------------------------------------------------------
// Row softmax over 1024
// ---------------------------------------------------------------------------
__global__ void softmax_kernel(float* __restrict__ S)
{
    __shared__ float sh[8];
    size_t row = blockIdx.x;
    float* p = S + row * HWW;
    int t = threadIdx.x;

    float4 v = ((const float4*)p)[t];
    float m = fmaxf(fmaxf(v.x, v.y), fmaxf(v.z, v.w));
    #pragma unroll
    for (int o = 16; o > 0; o >>= 1) m = fmaxf(m, __shfl_xor_sync(0xffffffffu, m, o));
    if ((t & 31) == 0) sh[t >> 5] = m;
    __syncthreads();
    float M = sh[0];
    #pragma unroll
    for (int i = 1; i < 8; i++) M = fmaxf(M, sh[i]);
    __syncthreads();

    v.x = __expf(v.x - M); v.y = __expf(v.y - M);
    v.z = __expf(v.z - M); v.w = __expf(v.w - M);
    float s = v.x + v.y + v.z + v.w;
    #pragma unroll
    for (int o = 16; o > 0; o >>= 1) s += __shfl_xor_sync(0xffffffffu, s, o);
    if ((t & 31) == 0) sh[t >> 5] = s;
    __syncthreads();
    float T = 0.f;
    #pragma unroll
    for (int i = 0; i < 8; i++) T += sh[i];
    float inv = 1.0f / T;

    v.x *= inv; v.y *= inv; v.z *= inv; v.w *= inv;
    ((float4*)p)[t] = v;
}

// ---------------------------------------------------------------------------
extern "C" void kernel_launch(void* const* d_in, const int* in_sizes, int n_in,
                              void* d_out, int out_size)
{
    const float* x   = (const float*)d_in[0];
    const float* y   = (const float*)d_in[1];
    const float* ns  = (const float*)d_in[2];
    const float* nb  = (const float*)d_in[3];
    const float* n1s = (const float*)d_in[4];
    const float* n1b = (const float*)d_in[5];
    const float* wq  = (const float*)d_in[6];
    const float* bq  = (const float*)d_in[7];
    const float* wk  = (const float*)d_in[8];
    const float* bk  = (const float*)d_in[9];
    const float* wv  = (const float*)d_in[10];
    const float* bv  = (const float*)d_in[11];
    const float* wp  = (const float*)d_in[12];
    const float* bp  = (const float*)d_in[13];
    float* out = (float*)d_out;

    float *hxT, *hyT, *qT, *kT, *vT, *v2, *s;
    cudaGetSymbolAddress((void**)&hxT, g_hxT);
    cudaGetSymbolAddress((void**)&hyT, g_hyT);
    cudaGetSymbolAddress((void**)&qT,  g_qT);
    cudaGetSymbolAddress((void**)&kT,  g_kT);
    cudaGetSymbolAddress((void**)&vT,  g_vT);
    cudaGetSymbolAddress((void**)&v2,  g_v2);
    cudaGetSymbolAddress((void**)&s,   g_s);
    float* O = hxT;   // hxT dead after k,v GEMMs

    const int SMEM_GEMM = 4 * 2 * 128 * 20 * 4;      // 81920 B
    const int SMEM_GN   = 16 * 1026 * sizeof(float); // 65664 B
    cudaFuncSetAttribute(mma_gemm<0>, cudaFuncAttributeMaxDynamicSharedMemorySize, SMEM_GEMM);
    cudaFuncSetAttribute(mma_gemm<1>, cudaFuncAttributeMaxDynamicSharedMemorySize, SMEM_GEMM);
    cudaFuncSetAttribute(mma_gemm<2>, cudaFuncAttributeMaxDynamicSharedMemorySize, SMEM_GEMM);
    cudaFuncSetAttribute(mma_gemm<3>, cudaFuncAttributeMaxDynamicSharedMemorySize, SMEM_GEMM);
    cudaFuncSetAttribute(gn_t_kernel, cudaFuncAttributeMaxDynamicSharedMemorySize, SMEM_GN);

    const long AS = (long)CC * HWW;
    const long SS = (long)HWW * HWW;
    const float qkscale = 0.044194173824159216f;   // 512^-0.5

    gn_t_kernel<<<BB * 32, 256, SMEM_GN>>>(x, ns,  nb,  hxT);
    gn_t_kernel<<<BB * 32, 256, SMEM_GN>>>(y, n1s, n1b, hyT);

    // q/k/v: D[hw, oc] = sum_c actT[hw,c] * W[oc,c] + b[oc]
    dim3 gqkv(CC / 128, HWW / 128, BB);   // (4, 8, 16)
    mma_gemm<0><<<gqkv, 256, SMEM_GEMM>>>(hyT, wq, qT, bq, nullptr, 32, CC, CC, CC, AS, 0, AS, 0.f);
    mma_gemm<0><<<gqkv, 256, SMEM_GEMM>>>(hxT, wk, kT, bk, nullptr, 32, CC, CC, CC, AS, 0, AS, 0.f);
    mma_gemm<0><<<gqkv, 256, SMEM_GEMM>>>(hxT, wv, vT, bv, nullptr, 32, CC, CC, CC, AS, 0, AS, 0.f);

    transpose_kernel<<<dim3(HWW / 32, CC / 32, BB), 256>>>(vT, v2);

    // scores: S[i,j] = scale * sum_c qT[i,c] * kT[j,c]
    dim3 gqk(HWW / 128, HWW / 128, BB);   // (8, 8, 16)
    mma_gemm<1><<<gqk, 256, SMEM_GEMM>>>(qT, kT, s, nullptr, nullptr, 32, CC, CC, HWW, AS, AS, SS, qkscale);

    softmax_kernel<<<BB * HWW, 256>>>(s);

    // O[i, c] = sum_j attn[i,j] * v2[c,j]
    dim3 gav(CC / 128, HWW / 128, BB);    // (4, 8, 16)
    mma_gemm<2><<<gav, 256, SMEM_GEMM>>>(s, v2, O, nullptr, nullptr, 64, HWW, HWW, CC, SS, AS, AS, 0.f);

    // out[oc, hw] = sum_c wp[oc,c] * O[hw,c] + bp[oc] + x
    dim3 gproj(HWW / 128, CC / 128, BB);  // (8, 4, 16)
    mma_gemm<3><<<gproj, 256, SMEM_GEMM>>>(wp, O, out, bp, x, 32, CC, CC, HWW, 0, AS, AS, 0.f);
}

// round 7
// speedup vs baseline: 1.1581x; 1.1581x over previous
#include <cuda_runtime.h>
#include <cstdint>
#include <math.h>

#define BB   16
#define CC   512
#define HWW  1024
#define ABUF ((size_t)BB*CC*HWW)      // 8M floats = 32MB

// Scratch (__device__ globals; no allocs allowed)
__device__ float g_hxT[ABUF];   // normalized x, [b][hw][c]; reused as O after k,v
__device__ float g_hyT[ABUF];   // normalized y, [b][hw][c]
__device__ float g_qT [ABUF];   // [b][hw][c]
__device__ float g_kT [ABUF];   // [b][hw][c]
__device__ float g_vT [ABUF];   // [b][hw][c]
__device__ float g_v2 [ABUF];   // [b][c][hw]
__device__ float g_s  [(size_t)BB*HWW*HWW];  // 64MB scores

__device__ __forceinline__ uint32_t smem_u32(const void* p) {
    uint32_t a;
    asm("{ .reg .u64 t; cvta.to.shared.u64 t, %1; cvt.u32.u64 %0, t; }" : "=r"(a) : "l"(p));
    return a;
}
#define CP_ASYNC16(sa, ga) \
    asm volatile("cp.async.cg.shared.global [%0], [%1], 16;" :: "r"(sa), "l"(ga) : "memory")
#define CP_COMMIT() asm volatile("cp.async.commit_group;" ::: "memory")
#define CP_WAIT1()  asm volatile("cp.async.wait_group 1;" ::: "memory")
#define CP_WAIT0()  asm volatile("cp.async.wait_group 0;" ::: "memory")

// ---------------------------------------------------------------------------
// tf32 mma.sync GEMM: D[m,n] = sum_k A[m,k]*B[n,k]; 128x128 block tile,
// 2-stage cp.async (K-chunk 32). 4 warps, warp tile 64x64 (4x8 m16n8k8),
// register double-buffered fragments across 8-K steps (LDS hidden under MMAs).
// Smem [128][36]: fragment LDS banks (4g+tg)%32 all-distinct, conflict-free.
// EPI: 0 = +bias[n] | 1 = *scale | 2 = none | 3 = +bias[m]+resid
// ---------------------------------------------------------------------------
template<int EPI>
__global__ __launch_bounds__(128, 2)
void mma_gemm(const float* __restrict__ A, const float* __restrict__ B,
              float* __restrict__ C, const float* __restrict__ bias,
              const float* __restrict__ resid,
              int NC, int lda, int ldb, int ldc,
              long aB, long bB, long cB, float scale)
{
    extern __shared__ float sm[];    // 2 stages x (A 128*36 + B 128*36)
    const int TP = 36, TILE = 128 * TP, STG = 2 * TILE;   // floats

    int t = threadIdx.x, lane = t & 31, w = t >> 5;
    int wr = w & 1, wc = w >> 1;          // warp grid 2 x 2, warp tile 64x64
    int g = lane >> 2, tg = lane & 3;
    int bz = blockIdx.z, m0 = blockIdx.y * 128, n0 = blockIdx.x * 128;
    const float* Ab = A + (size_t)bz * aB;
    const float* Bb = B + (size_t)bz * bB;
    float*       Cb = C + (size_t)bz * cB;
    uint32_t smb = smem_u32(sm);

    // Stage load: A tile 128x32 + B tile 128x32; 1024 float4 chunks per tile,
    // 128 threads -> 8 chunks per thread per tile. Quarter-warp rows contiguous.
    auto load = [&](int c, int s) {
        int k0 = c * 32;
        #pragma unroll
        for (int j = 0; j < 8; j++) {
            int idx = t + 128 * j;          // 0..1023
            int r = idx >> 3, cq = (idx & 7) * 4;
            const float* ga = Ab + (size_t)(m0 + r) * lda + k0 + cq;
            const float* gb = Bb + (size_t)(n0 + r) * ldb + k0 + cq;
            uint32_t sa  = smb + (uint32_t)(s * STG + r * TP + cq) * 4u;
            uint32_t sbm = smb + (uint32_t)(s * STG + TILE + r * TP + cq) * 4u;
            CP_ASYNC16(sa, ga);
            CP_ASYNC16(sbm, gb);
        }
    };

    float acc[4][8][4];
    #pragma unroll
    for (int i = 0; i < 4; i++)
        #pragma unroll
        for (int j = 0; j < 8; j++)
            #pragma unroll
            for (int q = 0; q < 4; q++) acc[i][j][q] = 0.f;

    // Fragment loader for one 8-K step
    auto ldfrag = [&](const float* As, const float* Bs, int kk,
                      uint32_t (&af)[4][4], uint32_t (&bf)[8][2]) {
        #pragma unroll
        for (int i = 0; i < 4; i++) {
            const float* ap = As + (size_t)(wr * 64 + i * 16 + g) * TP + kk + tg;
            af[i][0] = __float_as_uint(ap[0]);
            af[i][1] = __float_as_uint(ap[8 * TP]);
            af[i][2] = __float_as_uint(ap[4]);
            af[i][3] = __float_as_uint(ap[8 * TP + 4]);
        }
        #pragma unroll
        for (int j = 0; j < 8; j++) {
            const float* bp = Bs + (size_t)(wc * 64 + j * 8 + g) * TP + kk + tg;
            bf[j][0] = __float_as_uint(bp[0]);
            bf[j][1] = __float_as_uint(bp[4]);
        }
    };

    load(0, 0); CP_COMMIT();
    if (NC > 1) { load(1, 1); CP_COMMIT(); }

    uint32_t af[2][4][4], bf[2][8][2];

    for (int c = 0; c < NC; c++) {
        if (c + 1 < NC) CP_WAIT1(); else CP_WAIT0();
        __syncthreads();
        const float* As = sm + (c & 1) * STG;
        const float* Bs = As + TILE;

        ldfrag(As, Bs, 0, af[0], bf[0]);
        #pragma unroll
        for (int s8 = 0; s8 < 4; s8++) {
            // Prefetch next step's fragments before issuing this step's MMAs
            if (s8 < 3) ldfrag(As, Bs, (s8 + 1) * 8, af[(s8 + 1) & 1], bf[(s8 + 1) & 1]);
            uint32_t (&a)[4][4] = af[s8 & 1];
            uint32_t (&b)[8][2] = bf[s8 & 1];
            #pragma unroll
            for (int i = 0; i < 4; i++)
                #pragma unroll
                for (int j = 0; j < 8; j++)
                    asm volatile(
                        "mma.sync.aligned.m16n8k8.row.col.f32.tf32.tf32.f32 "
                        "{%0,%1,%2,%3},{%4,%5,%6,%7},{%8,%9},{%0,%1,%2,%3};"
                        : "+f"(acc[i][j][0]), "+f"(acc[i][j][1]),
                          "+f"(acc[i][j][2]), "+f"(acc[i][j][3])
                        : "r"(a[i][0]), "r"(a[i][1]), "r"(a[i][2]), "r"(a[i][3]),
                          "r"(b[j][0]), "r"(b[j][1]));
        }
        __syncthreads();
        if (c + 2 < NC) { load(c + 2, c & 1); CP_COMMIT(); }
    }

    // Epilogue: acc[i][j] -> rows m0+wr*64+i*16+{g,g+8}, cols n0+wc*64+j*8+2*tg
    int mrow = m0 + wr * 64;
    int ncol = n0 + wc * 64;
    #pragma unroll
    for (int i = 0; i < 4; i++) {
        int r0 = mrow + i * 16 + g, r1 = r0 + 8;
        float bm0 = 0.f, bm1 = 0.f;
        if (EPI == 3) { bm0 = __ldg(&bias[r0]); bm1 = __ldg(&bias[r1]); }
        #pragma unroll
        for (int j = 0; j < 8; j++) {
            int cc = ncol + j * 8 + 2 * tg;
            float2 v0 = make_float2(acc[i][j][0], acc[i][j][1]);
            float2 v1 = make_float2(acc[i][j][2], acc[i][j][3]);
            if (EPI == 0) {
                float b0 = __ldg(&bias[cc]), b1 = __ldg(&bias[cc + 1]);
                v0.x += b0; v0.y += b1; v1.x += b0; v1.y += b1;
            } else if (EPI == 1) {
                v0.x *= scale; v0.y *= scale; v1.x *= scale; v1.y *= scale;
            } else if (EPI == 3) {
                const float* Rb = resid + (size_t)bz * cB;
                float2 x0 = *(const float2*)(Rb + (size_t)r0 * ldc + cc);
                float2 x1 = *(const float2*)(Rb + (size_t)r1 * ldc + cc);
                v0.x += bm0 + x0.x; v0.y += bm0 + x0.y;
                v1.x += bm1 + x1.x; v1.y += bm1 + x1.y;
            }
            *(float2*)(Cb + (size_t)r0 * ldc + cc) = v0;
            *(float2*)(Cb + (size_t)r1 * ldc + cc) = v1;
        }
    }
}

// ---------------------------------------------------------------------------
// GroupNorm with transposed output [b][hw][c]. One block per (b, group).
// ---------------------------------------------------------------------------
__global__ void gn_t_kernel(const float* __restrict__ x, const float* __restrict__ sc,
                            const float* __restrict__ bi, float* __restrict__ outT)
{
    extern __shared__ float xs[];      // 16 * 1026
    __shared__ float shs[8], shq[8], shm[2];
    int bg = blockIdx.x;
    int b = bg >> 5, g = bg & 31;
    const float* xp = x + ((size_t)b * CC + (size_t)g * 16) * HWW;
    int t = threadIdx.x;

    float s = 0.f, sq = 0.f;
    #pragma unroll 4
    for (int j = 0; j < 64; j++) {
        int idx = t + 256 * j;               // idx = c*1024 + hw
        float v = xp[idx];
        xs[(idx >> 10) * 1026 + (idx & 1023)] = v;
        s += v; sq += v * v;
    }
    #pragma unroll
    for (int o = 16; o > 0; o >>= 1) {
        s  += __shfl_xor_sync(0xffffffffu, s,  o);
        sq += __shfl_xor_sync(0xffffffffu, sq, o);
    }
    if ((t & 31) == 0) { shs[t >> 5] = s; shq[t >> 5] = sq; }
    __syncthreads();
    if (t == 0) {
        float S = 0.f, Q = 0.f;
        #pragma unroll
        for (int i = 0; i < 8; i++) { S += shs[i]; Q += shq[i]; }
        float mean = S * (1.f / 16384.f);
        float var  = Q * (1.f / 16384.f) - mean * mean;
        shm[0] = mean;
        shm[1] = rsqrtf(var + 1e-6f);
    }
    __syncthreads();
    float mean = shm[0], rs = shm[1];
    int cl = t & 15;
    float scv = __ldg(&sc[g * 16 + cl]) * rs;
    float biv = __ldg(&bi[g * 16 + cl]);
    float* op = outT + (size_t)b * HWW * CC + g * 16;
    #pragma unroll 4
    for (int j = 0; j < 64; j++) {
        int idx = t + 256 * j;
        int hw = idx >> 4;
        op[(size_t)hw * CC + cl] = (xs[cl * 1026 + hw] - mean) * scv + biv;
    }
}

// ---------------------------------------------------------------------------
// 32x32 tiled transpose: vT [b][hw][c] -> v2 [b][c][hw]
// ---------------------------------------------------------------------------
__global__ void transpose_kernel(const float* __restrict__ vT, float* __restrict__ v2)
{
    __shared__ float ts[32][33];
    int b = blockIdx.z;
    int hw0 = blockIdx.x * 32, c0 = blockIdx.y * 32;
    const float* src = vT + (size_t)b * CC * HWW;
    float*       dst = v2 + (size_t)b * CC * HWW;
    int t = threadIdx.x, tx = t & 31, ty = t >> 5;
    #pragma unroll
    for (int i = 0; i < 4; i++) {
        int hw = hw0 + ty + i * 8;
        ts[ty + i * 8][tx] = src[(size_t)hw * CC + c0 + tx];
    }
    __syncthreads();
    #pragma unroll
    for (int i = 0; i < 4; i++) {
        int c = c0 + ty + i * 8;
        dst[(size_t)c * HWW + hw0 + tx] = ts[tx][ty + i * 8];
    }
}

// ---------------------------------------------------------------------------
// Row softmax over 1024
// ---------------------------------------------------------------------------
__global__ void softmax_kernel(float* __restrict__ S)
{
    __shared__ float sh[8];
    size_t row = blockIdx.x;
    float* p = S + row * HWW;
    int t = threadIdx.x;

    float4 v = ((const float4*)p)[t];
    float m = fmaxf(fmaxf(v.x, v.y), fmaxf(v.z, v.w));
    #pragma unroll
    for (int o = 16; o > 0; o >>= 1) m = fmaxf(m, __shfl_xor_sync(0xffffffffu, m, o));
    if ((t & 31) == 0) sh[t >> 5] = m;
    __syncthreads();
    float M = sh[0];
    #pragma unroll
    for (int i = 1; i < 8; i++) M = fmaxf(M, sh[i]);
    __syncthreads();

    v.x = __expf(v.x - M); v.y = __expf(v.y - M);
    v.z = __expf(v.z - M); v.w = __expf(v.w - M);
    float s = v.x + v.y + v.z + v.w;
    #pragma unroll
    for (int o = 16; o > 0; o >>= 1) s += __shfl_xor_sync(0xffffffffu, s, o);
    if ((t & 31) == 0) sh[t >> 5] = s;
    __syncthreads();
    float T = 0.f;
    #pragma unroll
    for (int i = 0; i < 8; i++) T += sh[i];
    float inv = 1.0f / T;

    v.x *= inv; v.y *= inv; v.z *= inv; v.w *= inv;
    ((float4*)p)[t] = v;
}

// ---------------------------------------------------------------------------
extern "C" void kernel_launch(void* const* d_in, const int* in_sizes, int n_in,
                              void* d_out, int out_size)
{
    const float* x   = (const float*)d_in[0];
    const float* y   = (const float*)d_in[1];
    const float* ns  = (const float*)d_in[2];
    const float* nb  = (const float*)d_in[3];
    const float* n1s = (const float*)d_in[4];
    const float* n1b = (const float*)d_in[5];
    const float* wq  = (const float*)d_in[6];
    const float* bq  = (const float*)d_in[7];
    const float* wk  = (const float*)d_in[8];
    const float* bk  = (const float*)d_in[9];
    const float* wv  = (const float*)d_in[10];
    const float* bv  = (const float*)d_in[11];
    const float* wp  = (const float*)d_in[12];
    const float* bp  = (const float*)d_in[13];
    float* out = (float*)d_out;

    float *hxT, *hyT, *qT, *kT, *vT, *v2, *s;
    cudaGetSymbolAddress((void**)&hxT, g_hxT);
    cudaGetSymbolAddress((void**)&hyT, g_hyT);
    cudaGetSymbolAddress((void**)&qT,  g_qT);
    cudaGetSymbolAddress((void**)&kT,  g_kT);
    cudaGetSymbolAddress((void**)&vT,  g_vT);
    cudaGetSymbolAddress((void**)&v2,  g_v2);
    cudaGetSymbolAddress((void**)&s,   g_s);
    float* O = hxT;   // hxT dead after k,v GEMMs

    const int SMEM_GEMM = 2 * 2 * 128 * 36 * 4;      // 73728 B
    const int SMEM_GN   = 16 * 1026 * sizeof(float); // 65664 B
    cudaFuncSetAttribute(mma_gemm<0>, cudaFuncAttributeMaxDynamicSharedMemorySize, SMEM_GEMM);
    cudaFuncSetAttribute(mma_gemm<1>, cudaFuncAttributeMaxDynamicSharedMemorySize, SMEM_GEMM);
    cudaFuncSetAttribute(mma_gemm<2>, cudaFuncAttributeMaxDynamicSharedMemorySize, SMEM_GEMM);
    cudaFuncSetAttribute(mma_gemm<3>, cudaFuncAttributeMaxDynamicSharedMemorySize, SMEM_GEMM);
    cudaFuncSetAttribute(gn_t_kernel, cudaFuncAttributeMaxDynamicSharedMemorySize, SMEM_GN);

    const long AS = (long)CC * HWW;
    const long SS = (long)HWW * HWW;
    const float qkscale = 0.044194173824159216f;   // 512^-0.5

    gn_t_kernel<<<BB * 32, 256, SMEM_GN>>>(x, ns,  nb,  hxT);
    gn_t_kernel<<<BB * 32, 256, SMEM_GN>>>(y, n1s, n1b, hyT);

    // q/k/v: D[hw, oc] = sum_c actT[hw,c] * W[oc,c] + b[oc]
    dim3 gqkv(CC / 128, HWW / 128, BB);   // (4, 8, 16)
    mma_gemm<0><<<gqkv, 128, SMEM_GEMM>>>(hyT, wq, qT, bq, nullptr, 16, CC, CC, CC, AS, 0, AS, 0.f);
    mma_gemm<0><<<gqkv, 128, SMEM_GEMM>>>(hxT, wk, kT, bk, nullptr, 16, CC, CC, CC, AS, 0, AS, 0.f);
    mma_gemm<0><<<gqkv, 128, SMEM_GEMM>>>(hxT, wv, vT, bv, nullptr, 16, CC, CC, CC, AS, 0, AS, 0.f);

    transpose_kernel<<<dim3(HWW / 32, CC / 32, BB), 256>>>(vT, v2);

    // scores: S[i,j] = scale * sum_c qT[i,c] * kT[j,c]
    dim3 gqk(HWW / 128, HWW / 128, BB);   // (8, 8, 16)
    mma_gemm<1><<<gqk, 128, SMEM_GEMM>>>(qT, kT, s, nullptr, nullptr, 16, CC, CC, HWW, AS, AS, SS, qkscale);

    softmax_kernel<<<BB * HWW, 256>>>(s);

    // O[i, c] = sum_j attn[i,j] * v2[c,j]
    dim3 gav(CC / 128, HWW / 128, BB);    // (4, 8, 16)
    mma_gemm<2><<<gav, 128, SMEM_GEMM>>>(s, v2, O, nullptr, nullptr, 32, HWW, HWW, CC, SS, AS, AS, 0.f);

    // out[oc, hw] = sum_c wp[oc,c] * O[hw,c] + bp[oc] + x
    dim3 gproj(HWW / 128, CC / 128, BB);  // (8, 4, 16)
    mma_gemm<3><<<gproj, 128, SMEM_GEMM>>>(wp, O, out, bp, x, 16, CC, CC, HWW, 0, AS, AS, 0.f);
}

// round 8
// speedup vs baseline: 1.3425x; 1.1592x over previous
#include <cuda_runtime.h>
#include <cstdint>
#include <math.h>

#define BB   16
#define CC   512
#define HWW  1024
#define ABUF ((size_t)BB*CC*HWW)      // 8M floats = 32MB

// Scratch (__device__ globals; no allocs allowed)
__device__ float g_hxT[ABUF];   // normalized x, [b][hw][c]; reused as O after k,v
__device__ float g_hyT[ABUF];   // normalized y, [b][hw][c]
__device__ float g_qT [ABUF];   // [b][hw][c]
__device__ float g_kT [ABUF];   // [b][hw][c]
__device__ float g_vT [ABUF];   // [b][hw][c]
__device__ float g_v2 [ABUF];   // [b][c][hw]
__device__ float g_s  [(size_t)BB*HWW*HWW];  // 64MB scores

__device__ __forceinline__ uint32_t smem_u32(const void* p) {
    uint32_t a;
    asm("{ .reg .u64 t; cvta.to.shared.u64 t, %1; cvt.u32.u64 %0, t; }" : "=r"(a) : "l"(p));
    return a;
}
#define CP_ASYNC16(sa, ga) \
    asm volatile("cp.async.cg.shared.global [%0], [%1], 16;" :: "r"(sa), "l"(ga) : "memory")
#define CP_COMMIT() asm volatile("cp.async.commit_group;" ::: "memory")
#define CP_WAIT1()  asm volatile("cp.async.wait_group 1;" ::: "memory")
#define CP_WAIT0()  asm volatile("cp.async.wait_group 0;" ::: "memory")

// ---------------------------------------------------------------------------
// tf32 mma.sync GEMM: D[m,n] = sum_k A[m,k]*B[n,k]; 128x128 block tile.
// 3-stage cp.async pipeline (K-chunk 32), ONE __syncthreads per chunk, loads
// for chunk c+2 issued at top of chunk c (2-chunk prefetch distance).
// 4 warps, warp tile 64x64 (4x8 m16n8k8), register double-buffered fragments.
// Smem: TP=32 with chunk-XOR swizzle (chunk' = chunk ^ (row&7)):
//   - fragment LDS banks 4*(chunk^g)+tg -> all 32 distinct per warp
//   - cp.async 16B stores: row's 8 chunks permuted, full-row bank coverage
// Stage rotation mod 3: iter c reads stage c%3, writes (c+2)%3 = (c-1)%3.
// EPI: 0 = +bias[n] | 1 = *scale | 2 = none | 3 = +bias[m]+resid
// ---------------------------------------------------------------------------
template<int EPI>
__global__ __launch_bounds__(128, 2)
void mma_gemm(const float* __restrict__ A, const float* __restrict__ B,
              float* __restrict__ C, const float* __restrict__ bias,
              const float* __restrict__ resid,
              int NC, int lda, int ldb, int ldc,
              long aB, long bB, long cB, float scale)
{
    extern __shared__ float sm[];    // 3 stages x (A 128*32 + B 128*32)
    const int TP = 32, TILE = 128 * TP, STG = 2 * TILE;   // floats

    int t = threadIdx.x, lane = t & 31, w = t >> 5;
    int wr = w & 1, wc = w >> 1;          // warp grid 2 x 2, warp tile 64x64
    int g = lane >> 2, tg = lane & 3;
    int bz = blockIdx.z, m0 = blockIdx.y * 128, n0 = blockIdx.x * 128;
    const float* Ab = A + (size_t)bz * aB;
    const float* Bb = B + (size_t)bz * bB;
    float*       Cb = C + (size_t)bz * cB;
    uint32_t smb = smem_u32(sm);

    // Stage load: A tile 128x32 + B tile 128x32; 1024 float4 chunks per tile,
    // 128 threads -> 8 chunks per thread per tile. XOR-swizzled chunk slot.
    auto load = [&](int c, int s) {
        int k0 = c * 32;
        #pragma unroll
        for (int j = 0; j < 8; j++) {
            int idx = t + 128 * j;          // 0..1023
            int r = idx >> 3, cq = idx & 7;
            int cs = cq ^ (r & 7);          // swizzled chunk slot
            const float* ga = Ab + (size_t)(m0 + r) * lda + k0 + cq * 4;
            const float* gb = Bb + (size_t)(n0 + r) * ldb + k0 + cq * 4;
            uint32_t so = (uint32_t)(s * STG + r * TP + cs * 4) * 4u;
            CP_ASYNC16(smb + so, ga);
            CP_ASYNC16(smb + (uint32_t)(TILE * 4) + so, gb);
        }
    };

    float acc[4][8][4];
    #pragma unroll
    for (int i = 0; i < 4; i++)
        #pragma unroll
        for (int j = 0; j < 8; j++)
            #pragma unroll
            for (int q = 0; q < 4; q++) acc[i][j][q] = 0.f;

    // Fragment loader for one 8-K step (chunks 2*s8, 2*s8+1), XOR-swizzled
    auto ldfrag = [&](const float* As, const float* Bs, int s8,
                      uint32_t (&af)[4][4], uint32_t (&bf)[8][2]) {
        int ch0 = 2 * s8, ch1 = 2 * s8 + 1;
        int c0 = ((ch0 ^ g) << 2) + tg;     // swizzled col for chunk ch0
        int c1 = ((ch1 ^ g) << 2) + tg;     // swizzled col for chunk ch1
        #pragma unroll
        for (int i = 0; i < 4; i++) {
            const float* ap = As + (size_t)(wr * 64 + i * 16 + g) * TP;
            af[i][0] = __float_as_uint(ap[c0]);
            af[i][1] = __float_as_uint(ap[8 * TP + c0]);
            af[i][2] = __float_as_uint(ap[c1]);
            af[i][3] = __float_as_uint(ap[8 * TP + c1]);
        }
        #pragma unroll
        for (int j = 0; j < 8; j++) {
            const float* bp = Bs + (size_t)(wc * 64 + j * 8 + g) * TP;
            bf[j][0] = __float_as_uint(bp[c0]);
            bf[j][1] = __float_as_uint(bp[c1]);
        }
    };

    load(0, 0); CP_COMMIT();
    if (NC > 1) { load(1, 1); CP_COMMIT(); }

    uint32_t af[2][4][4], bf[2][8][2];

    for (int c = 0; c < NC; c++) {
        if (c + 1 < NC) CP_WAIT1(); else CP_WAIT0();   // stage c landed
        __syncthreads();                                // all warps done with stage (c-1)%3
        if (c + 2 < NC) { load(c + 2, (c + 2) % 3); CP_COMMIT(); }  // overlaps MMAs

        const float* As = sm + (c % 3) * STG;
        const float* Bs = As + TILE;

        ldfrag(As, Bs, 0, af[0], bf[0]);
        #pragma unroll
        for (int s8 = 0; s8 < 4; s8++) {
            // Prefetch next step's fragments before issuing this step's MMAs
            if (s8 < 3) ldfrag(As, Bs, s8 + 1, af[(s8 + 1) & 1], bf[(s8 + 1) & 1]);
            uint32_t (&a)[4][4] = af[s8 & 1];
            uint32_t (&b)[8][2] = bf[s8 & 1];
            #pragma unroll
            for (int i = 0; i < 4; i++)
                #pragma unroll
                for (int j = 0; j < 8; j++)
                    asm volatile(
                        "mma.sync.aligned.m16n8k8.row.col.f32.tf32.tf32.f32 "
                        "{%0,%1,%2,%3},{%4,%5,%6,%7},{%8,%9},{%0,%1,%2,%3};"
                        : "+f"(acc[i][j][0]), "+f"(acc[i][j][1]),
                          "+f"(acc[i][j][2]), "+f"(acc[i][j][3])
                        : "r"(a[i][0]), "r"(a[i][1]), "r"(a[i][2]), "r"(a[i][3]),
                          "r"(b[j][0]), "r"(b[j][1]));
        }
    }

    // Epilogue: acc[i][j] -> rows m0+wr*64+i*16+{g,g+8}, cols n0+wc*64+j*8+2*tg
    int mrow = m0 + wr * 64;
    int ncol = n0 + wc * 64;
    #pragma unroll
    for (int i = 0; i < 4; i++) {
        int r0 = mrow + i * 16 + g, r1 = r0 + 8;
        float bm0 = 0.f, bm1 = 0.f;
        if (EPI == 3) { bm0 = __ldg(&bias[r0]); bm1 = __ldg(&bias[r1]); }
        #pragma unroll
        for (int j = 0; j < 8; j++) {
            int cc = ncol + j * 8 + 2 * tg;
            float2 v0 = make_float2(acc[i][j][0], acc[i][j][1]);
            float2 v1 = make_float2(acc[i][j][2], acc[i][j][3]);
            if (EPI == 0) {
                float b0 = __ldg(&bias[cc]), b1 = __ldg(&bias[cc + 1]);
                v0.x += b0; v0.y += b1; v1.x += b0; v1.y += b1;
            } else if (EPI == 1) {
                v0.x *= scale; v0.y *= scale; v1.x *= scale; v1.y *= scale;
            } else if (EPI == 3) {
                const float* Rb = resid + (size_t)bz * cB;
                float2 x0 = *(const float2*)(Rb + (size_t)r0 * ldc + cc);
                float2 x1 = *(const float2*)(Rb + (size_t)r1 * ldc + cc);
                v0.x += bm0 + x0.x; v0.y += bm0 + x0.y;
                v1.x += bm1 + x1.x; v1.y += bm1 + x1.y;
            }
            *(float2*)(Cb + (size_t)r0 * ldc + cc) = v0;
            *(float2*)(Cb + (size_t)r1 * ldc + cc) = v1;
        }
    }
}

// ---------------------------------------------------------------------------
// GroupNorm with transposed output [b][hw][c]. One block per (b, group).
// ---------------------------------------------------------------------------
__global__ void gn_t_kernel(const float* __restrict__ x, const float* __restrict__ sc,
                            const float* __restrict__ bi, float* __restrict__ outT)
{
    extern __shared__ float xs[];      // 16 * 1026
    __shared__ float shs[8], shq[8], shm[2];
    int bg = blockIdx.x;
    int b = bg >> 5, g = bg & 31;
    const float* xp = x + ((size_t)b * CC + (size_t)g * 16) * HWW;
    int t = threadIdx.x;

    float s = 0.f, sq = 0.f;
    #pragma unroll 4
    for (int j = 0; j < 64; j++) {
        int idx = t + 256 * j;               // idx = c*1024 + hw
        float v = xp[idx];
        xs[(idx >> 10) * 1026 + (idx & 1023)] = v;
        s += v; sq += v * v;
    }
    #pragma unroll
    for (int o = 16; o > 0; o >>= 1) {
        s  += __shfl_xor_sync(0xffffffffu, s,  o);
        sq += __shfl_xor_sync(0xffffffffu, sq, o);
    }
    if ((t & 31) == 0) { shs[t >> 5] = s; shq[t >> 5] = sq; }
    __syncthreads();
    if (t == 0) {
        float S = 0.f, Q = 0.f;
        #pragma unroll
        for (int i = 0; i < 8; i++) { S += shs[i]; Q += shq[i]; }
        float mean = S * (1.f / 16384.f);
        float var  = Q * (1.f / 16384.f) - mean * mean;
        shm[0] = mean;
        shm[1] = rsqrtf(var + 1e-6f);
    }
    __syncthreads();
    float mean = shm[0], rs = shm[1];
    int cl = t & 15;
    float scv = __ldg(&sc[g * 16 + cl]) * rs;
    float biv = __ldg(&bi[g * 16 + cl]);
    float* op = outT + (size_t)b * HWW * CC + g * 16;
    #pragma unroll 4
    for (int j = 0; j < 64; j++) {
        int idx = t + 256 * j;
        int hw = idx >> 4;
        op[(size_t)hw * CC + cl] = (xs[cl * 1026 + hw] - mean) * scv + biv;
    }
}

// ---------------------------------------------------------------------------
// 32x32 tiled transpose: vT [b][hw][c] -> v2 [b][c][hw]
// ---------------------------------------------------------------------------
__global__ void transpose_kernel(const float* __restrict__ vT, float* __restrict__ v2)
{
    __shared__ float ts[32][33];
    int b = blockIdx.z;
    int hw0 = blockIdx.x * 32, c0 = blockIdx.y * 32;
    const float* src = vT + (size_t)b * CC * HWW;
    float*       dst = v2 + (size_t)b * CC * HWW;
    int t = threadIdx.x, tx = t & 31, ty = t >> 5;
    #pragma unroll
    for (int i = 0; i < 4; i++) {
        int hw = hw0 + ty + i * 8;
        ts[ty + i * 8][tx] = src[(size_t)hw * CC + c0 + tx];
    }
    __syncthreads();
    #pragma unroll
    for (int i = 0; i < 4; i++) {
        int c = c0 + ty + i * 8;
        dst[(size_t)c * HWW + hw0 + tx] = ts[tx][ty + i * 8];
    }
}

// ---------------------------------------------------------------------------
// Row softmax over 1024
// ---------------------------------------------------------------------------
__global__ void softmax_kernel(float* __restrict__ S)
{
    __shared__ float sh[8];
    size_t row = blockIdx.x;
    float* p = S + row * HWW;
    int t = threadIdx.x;

    float4 v = ((const float4*)p)[t];
    float m = fmaxf(fmaxf(v.x, v.y), fmaxf(v.z, v.w));
    #pragma unroll
    for (int o = 16; o > 0; o >>= 1) m = fmaxf(m, __shfl_xor_sync(0xffffffffu, m, o));
    if ((t & 31) == 0) sh[t >> 5] = m;
    __syncthreads();
    float M = sh[0];
    #pragma unroll
    for (int i = 1; i < 8; i++) M = fmaxf(M, sh[i]);
    __syncthreads();

    v.x = __expf(v.x - M); v.y = __expf(v.y - M);
    v.z = __expf(v.z - M); v.w = __expf(v.w - M);
    float s = v.x + v.y + v.z + v.w;
    #pragma unroll
    for (int o = 16; o > 0; o >>= 1) s += __shfl_xor_sync(0xffffffffu, s, o);
    if ((t & 31) == 0) sh[t >> 5] = s;
    __syncthreads();
    float T = 0.f;
    #pragma unroll
    for (int i = 0; i < 8; i++) T += sh[i];
    float inv = 1.0f / T;

    v.x *= inv; v.y *= inv; v.z *= inv; v.w *= inv;
    ((float4*)p)[t] = v;
}

// ---------------------------------------------------------------------------
extern "C" void kernel_launch(void* const* d_in, const int* in_sizes, int n_in,
                              void* d_out, int out_size)
{
    const float* x   = (const float*)d_in[0];
    const float* y   = (const float*)d_in[1];
    const float* ns  = (const float*)d_in[2];
    const float* nb  = (const float*)d_in[3];
    const float* n1s = (const float*)d_in[4];
    const float* n1b = (const float*)d_in[5];
    const float* wq  = (const float*)d_in[6];
    const float* bq  = (const float*)d_in[7];
    const float* wk  = (const float*)d_in[8];
    const float* bk  = (const float*)d_in[9];
    const float* wv  = (const float*)d_in[10];
    const float* bv  = (const float*)d_in[11];
    const float* wp  = (const float*)d_in[12];
    const float* bp  = (const float*)d_in[13];
    float* out = (float*)d_out;

    float *hxT, *hyT, *qT, *kT, *vT, *v2, *s;
    cudaGetSymbolAddress((void**)&hxT, g_hxT);
    cudaGetSymbolAddress((void**)&hyT, g_hyT);
    cudaGetSymbolAddress((void**)&qT,  g_qT);
    cudaGetSymbolAddress((void**)&kT,  g_kT);
    cudaGetSymbolAddress((void**)&vT,  g_vT);
    cudaGetSymbolAddress((void**)&v2,  g_v2);
    cudaGetSymbolAddress((void**)&s,   g_s);
    float* O = hxT;   // hxT dead after k,v GEMMs

    const int SMEM_GEMM = 3 * 2 * 128 * 32 * 4;      // 98304 B
    const int SMEM_GN   = 16 * 1026 * sizeof(float); // 65664 B
    cudaFuncSetAttribute(mma_gemm<0>, cudaFuncAttributeMaxDynamicSharedMemorySize, SMEM_GEMM);
    cudaFuncSetAttribute(mma_gemm<1>, cudaFuncAttributeMaxDynamicSharedMemorySize, SMEM_GEMM);
    cudaFuncSetAttribute(mma_gemm<2>, cudaFuncAttributeMaxDynamicSharedMemorySize, SMEM_GEMM);
    cudaFuncSetAttribute(mma_gemm<3>, cudaFuncAttributeMaxDynamicSharedMemorySize, SMEM_GEMM);
    cudaFuncSetAttribute(gn_t_kernel, cudaFuncAttributeMaxDynamicSharedMemorySize, SMEM_GN);

    const long AS = (long)CC * HWW;
    const long SS = (long)HWW * HWW;
    const float qkscale = 0.044194173824159216f;   // 512^-0.5

    gn_t_kernel<<<BB * 32, 256, SMEM_GN>>>(x, ns,  nb,  hxT);
    gn_t_kernel<<<BB * 32, 256, SMEM_GN>>>(y, n1s, n1b, hyT);

    // q/k/v: D[hw, oc] = sum_c actT[hw,c] * W[oc,c] + b[oc]
    dim3 gqkv(CC / 128, HWW / 128, BB);   // (4, 8, 16)
    mma_gemm<0><<<gqkv, 128, SMEM_GEMM>>>(hyT, wq, qT, bq, nullptr, 16, CC, CC, CC, AS, 0, AS, 0.f);
    mma_gemm<0><<<gqkv, 128, SMEM_GEMM>>>(hxT, wk, kT, bk, nullptr, 16, CC, CC, CC, AS, 0, AS, 0.f);
    mma_gemm<0><<<gqkv, 128, SMEM_GEMM>>>(hxT, wv, vT, bv, nullptr, 16, CC, CC, CC, AS, 0, AS, 0.f);

    transpose_kernel<<<dim3(HWW / 32, CC / 32, BB), 256>>>(vT, v2);

    // scores: S[i,j] = scale * sum_c qT[i,c] * kT[j,c]
    dim3 gqk(HWW / 128, HWW / 128, BB);   // (8, 8, 16)
    mma_gemm<1><<<gqk, 128, SMEM_GEMM>>>(qT, kT, s, nullptr, nullptr, 16, CC, CC, HWW, AS, AS, SS, qkscale);

    softmax_kernel<<<BB * HWW, 256>>>(s);

    // O[i, c] = sum_j attn[i,j] * v2[c,j]
    dim3 gav(CC / 128, HWW / 128, BB);    // (4, 8, 16)
    mma_gemm<2><<<gav, 128, SMEM_GEMM>>>(s, v2, O, nullptr, nullptr, 32, HWW, HWW, CC, SS, AS, AS, 0.f);

    // out[oc, hw] = sum_c wp[oc,c] * O[hw,c] + bp[oc] + x
    dim3 gproj(HWW / 128, CC / 128, BB);  // (8, 4, 16)
    mma_gemm<3><<<gproj, 128, SMEM_GEMM>>>(wp, O, out, bp, x, 16, CC, CC, HWW, 0, AS, AS, 0.f);
}

// round 10
// speedup vs baseline: 1.4396x; 1.0723x over previous
#include <cuda_runtime.h>
#include <cstdint>
#include <math.h>

#define BB   16
#define CC   512
#define HWW  1024
#define ABUF ((size_t)BB*CC*HWW)      // 8M floats = 32MB

// Scratch (__device__ globals; no allocs allowed)
__device__ float g_hxT[ABUF];   // normalized x, [b][hw][c]; reused as O after k,v
__device__ float g_hyT[ABUF];   // normalized y, [b][hw][c]
__device__ float g_qT [ABUF];   // [b][hw][c]
__device__ float g_kT [ABUF];   // [b][hw][c]
__device__ float g_v2 [ABUF];   // [b][c][hw]  (written directly by V GEMM, EPI=4)
__device__ float g_s  [(size_t)BB*HWW*HWW];  // 64MB scores

__device__ __forceinline__ uint32_t smem_u32(const void* p) {
    uint32_t a;
    asm("{ .reg .u64 t; cvta.to.shared.u64 t, %1; cvt.u32.u64 %0, t; }" : "=r"(a) : "l"(p));
    return a;
}
#define CP_ASYNC16(sa, ga) \
    asm volatile("cp.async.cg.shared.global [%0], [%1], 16;" :: "r"(sa), "l"(ga) : "memory")
#define CP_COMMIT() asm volatile("cp.async.commit_group;" ::: "memory")
#define CP_WAIT1()  asm volatile("cp.async.wait_group 1;" ::: "memory")
#define CP_WAIT0()  asm volatile("cp.async.wait_group 0;" ::: "memory")

// ---------------------------------------------------------------------------
// tf32 mma.sync GEMM: D[m,n] = sum_k A[m,k]*B[n,k]; 128x128 block tile.
// 3-stage cp.async pipeline (K-chunk 32), ONE __syncthreads per chunk; at the
// top of chunk c: ldfrag(0) issues first (starts LDS chains), then cp.async
// for chunk c+2 (issue work hides fragment latency), then the 4 MMA steps.
// 4 warps, warp tile 64x64 (4x8 m16n8k8), register double-buffered fragments.
// Smem: TP=32 with chunk-XOR swizzle (chunk' = chunk ^ (row&7)).
// EPI: 0=+bias[n] | 1=*scale | 2=none | 3=+bias[m]+resid
//      4=+bias[n] then TRANSPOSED store via smem (D[m][n] -> C[n][m])
// ---------------------------------------------------------------------------
template<int EPI>
__global__ __launch_bounds__(128, 2)
void mma_gemm(const float* __restrict__ A, const float* __restrict__ B,
              float* __restrict__ C, const float* __restrict__ bias,
              const float* __restrict__ resid,
              int NC, int lda, int ldb, int ldc,
              long aB, long bB, long cB, float scale)
{
    extern __shared__ float sm[];    // 3 stages x (A 128*32 + B 128*32) = 98304 B
    const int TP = 32, TILE = 128 * TP, STG = 2 * TILE;   // floats

    int t = threadIdx.x, lane = t & 31, w = t >> 5;
    int wr = w & 1, wc = w >> 1;          // warp grid 2 x 2, warp tile 64x64
    int g = lane >> 2, tg = lane & 3;
    int bz = blockIdx.z, m0 = blockIdx.y * 128, n0 = blockIdx.x * 128;
    const float* Ab = A + (size_t)bz * aB;
    const float* Bb = B + (size_t)bz * bB;
    float*       Cb = C + (size_t)bz * cB;
    uint32_t smb = smem_u32(sm);

    auto load = [&](int c, int s) {
        int k0 = c * 32;
        #pragma unroll
        for (int j = 0; j < 8; j++) {
            int idx = t + 128 * j;          // 0..1023
            int r = idx >> 3, cq = idx & 7;
            int cs = cq ^ (r & 7);          // swizzled chunk slot
            const float* ga = Ab + (size_t)(m0 + r) * lda + k0 + cq * 4;
            const float* gb = Bb + (size_t)(n0 + r) * ldb + k0 + cq * 4;
            uint32_t so = (uint32_t)(s * STG + r * TP + cs * 4) * 4u;
            CP_ASYNC16(smb + so, ga);
            CP_ASYNC16(smb + (uint32_t)(TILE * 4) + so, gb);
        }
    };

    float acc[4][8][4];
    #pragma unroll
    for (int i = 0; i < 4; i++)
        #pragma unroll
        for (int j = 0; j < 8; j++)
            #pragma unroll
            for (int q = 0; q < 4; q++) acc[i][j][q] = 0.f;

    auto ldfrag = [&](const float* As, const float* Bs, int s8,
                      uint32_t (&af)[4][4], uint32_t (&bf)[8][2]) {
        int ch0 = 2 * s8, ch1 = 2 * s8 + 1;
        int c0 = ((ch0 ^ g) << 2) + tg;
        int c1 = ((ch1 ^ g) << 2) + tg;
        #pragma unroll
        for (int i = 0; i < 4; i++) {
            const float* ap = As + (size_t)(wr * 64 + i * 16 + g) * TP;
            af[i][0] = __float_as_uint(ap[c0]);
            af[i][1] = __float_as_uint(ap[8 * TP + c0]);
            af[i][2] = __float_as_uint(ap[c1]);
            af[i][3] = __float_as_uint(ap[8 * TP + c1]);
        }
        #pragma unroll
        for (int j = 0; j < 8; j++) {
            const float* bp = Bs + (size_t)(wc * 64 + j * 8 + g) * TP;
            bf[j][0] = __float_as_uint(bp[c0]);
            bf[j][1] = __float_as_uint(bp[c1]);
        }
    };

    load(0, 0); CP_COMMIT();
    if (NC > 1) { load(1, 1); CP_COMMIT(); }

    uint32_t af[2][4][4], bf[2][8][2];

    for (int c = 0; c < NC; c++) {
        if (c + 1 < NC) CP_WAIT1(); else CP_WAIT0();   // stage c landed (own groups)
        __syncthreads();                                // cross-thread visibility
        const float* As = sm + (c % 3) * STG;
        const float* Bs = As + TILE;
        ldfrag(As, Bs, 0, af[0], bf[0]);                // start LDS chains first
        if (c + 2 < NC) { load(c + 2, (c + 2) % 3); CP_COMMIT(); }  // hides frag latency

        #pragma unroll
        for (int s8 = 0; s8 < 4; s8++) {
            if (s8 < 3) ldfrag(As, Bs, s8 + 1, af[(s8 + 1) & 1], bf[(s8 + 1) & 1]);
            uint32_t (&a)[4][4] = af[s8 & 1];
            uint32_t (&b)[8][2] = bf[s8 & 1];
            #pragma unroll
            for (int i = 0; i < 4; i++)
                #pragma unroll
                for (int j = 0; j < 8; j++)
                    asm volatile(
                        "mma.sync.aligned.m16n8k8.row.col.f32.tf32.tf32.f32 "
                        "{%0,%1,%2,%3},{%4,%5,%6,%7},{%8,%9},{%0,%1,%2,%3};"
                        : "+f"(acc[i][j][0]), "+f"(acc[i][j][1]),
                          "+f"(acc[i][j][2]), "+f"(acc[i][j][3])
                        : "r"(a[i][0]), "r"(a[i][1]), "r"(a[i][2]), "r"(a[i][3]),
                          "r"(b[j][0]), "r"(b[j][1]));
        }
    }

    int mrow = m0 + wr * 64;
    int ncol = n0 + wc * 64;

    if (EPI == 4) {
        // +bias[n], then transposed store: D[m][n] -> C[n][m] via smem staging.
        // Staging pad 129: scatter stores ~2-way conflicts (epilogue-only);
        // read-back banks (rloc + lane) mod 32 -> conflict-free scalar reads.
        __syncthreads();                  // all warps done with mainloop smem
        #pragma unroll
        for (int i = 0; i < 4; i++) {
            int rl0 = wr * 64 + i * 16 + g, rl1 = rl0 + 8;
            #pragma unroll
            for (int j = 0; j < 8; j++) {
                int nl = wc * 64 + j * 8 + 2 * tg;
                float b0 = __ldg(&bias[n0 + nl]), b1 = __ldg(&bias[n0 + nl + 1]);
                sm[(nl + 0) * 129 + rl0] = acc[i][j][0] + b0;
                sm[(nl + 1) * 129 + rl0] = acc[i][j][1] + b1;
                sm[(nl + 0) * 129 + rl1] = acc[i][j][2] + b0;
                sm[(nl + 1) * 129 + rl1] = acc[i][j][3] + b1;
            }
        }
        __syncthreads();
        // Warp w writes local rows w*32..w*32+31; per row, 32 lanes write
        // scalar floats at lane+32k -> coalesced 128B STG transactions.
        #pragma unroll 4
        for (int rr = 0; rr < 32; rr++) {
            int rloc = w * 32 + rr;
            float* dst = Cb + (size_t)(n0 + rloc) * ldc + m0;
            const float* srcr = sm + rloc * 129;
            #pragma unroll
            for (int k2 = 0; k2 < 4; k2++)
                dst[lane + 32 * k2] = srcr[lane + 32 * k2];
        }
        return;
    }

    #pragma unroll
    for (int i = 0; i < 4; i++) {
        int r0 = mrow + i * 16 + g, r1 = r0 + 8;
        float bm0 = 0.f, bm1 = 0.f;
        if (EPI == 3) { bm0 = __ldg(&bias[r0]); bm1 = __ldg(&bias[r1]); }
        #pragma unroll
        for (int j = 0; j < 8; j++) {
            int cc = ncol + j * 8 + 2 * tg;
            float2 v0 = make_float2(acc[i][j][0], acc[i][j][1]);
            float2 v1 = make_float2(acc[i][j][2], acc[i][j][3]);
            if (EPI == 0) {
                float b0 = __ldg(&bias[cc]), b1 = __ldg(&bias[cc + 1]);
                v0.x += b0; v0.y += b1; v1.x += b0; v1.y += b1;
            } else if (EPI == 1) {
                v0.x *= scale; v0.y *= scale; v1.x *= scale; v1.y *= scale;
            } else if (EPI == 3) {
                const float* Rb = resid + (size_t)bz * cB;
                float2 x0 = *(const float2*)(Rb + (size_t)r0 * ldc + cc);
                float2 x1 = *(const float2*)(Rb + (size_t)r1 * ldc + cc);
                v0.x += bm0 + x0.x; v0.y += bm0 + x0.y;
                v1.x += bm1 + x1.x; v1.y += bm1 + x1.y;
            }
            *(float2*)(Cb + (size_t)r0 * ldc + cc) = v0;
            *(float2*)(Cb + (size_t)r1 * ldc + cc) = v1;
        }
    }
}

// ---------------------------------------------------------------------------
// GroupNorm with transposed output [b][hw][c]. One block per (b, group).
// ---------------------------------------------------------------------------
__global__ void gn_t_kernel(const float* __restrict__ x, const float* __restrict__ sc,
                            const float* __restrict__ bi, float* __restrict__ outT)
{
    extern __shared__ float xs[];      // 16 * 1026
    __shared__ float shs[8], shq[8], shm[2];
    int bg = blockIdx.x;
    int b = bg >> 5, g = bg & 31;
    const float* xp = x + ((size_t)b * CC + (size_t)g * 16) * HWW;
    int t = threadIdx.x;

    float s = 0.f, sq = 0.f;
    #pragma unroll 4
    for (int j = 0; j < 64; j++) {
        int idx = t + 256 * j;               // idx = c*1024 + hw
        float v = xp[idx];
        xs[(idx >> 10) * 1026 + (idx & 1023)] = v;
        s += v; sq += v * v;
    }
    #pragma unroll
    for (int o = 16; o > 0; o >>= 1) {
        s  += __shfl_xor_sync(0xffffffffu, s,  o);
        sq += __shfl_xor_sync(0xffffffffu, sq, o);
    }
    if ((t & 31) == 0) { shs[t >> 5] = s; shq[t >> 5] = sq; }
    __syncthreads();
    if (t == 0) {
        float S = 0.f, Q = 0.f;
        #pragma unroll
        for (int i = 0; i < 8; i++) { S += shs[i]; Q += shq[i]; }
        float mean = S * (1.f / 16384.f);
        float var  = Q * (1.f / 16384.f) - mean * mean;
        shm[0] = mean;
        shm[1] = rsqrtf(var + 1e-6f);
    }
    __syncthreads();
    float mean = shm[0], rs = shm[1];
    int cl = t & 15;
    float scv = __ldg(&sc[g * 16 + cl]) * rs;
    float biv = __ldg(&bi[g * 16 + cl]);
    float* op = outT + (size_t)b * HWW * CC + g * 16;
    #pragma unroll 4
    for (int j = 0; j < 64; j++) {
        int idx = t + 256 * j;
        int hw = idx >> 4;
        op[(size_t)hw * CC + cl] = (xs[cl * 1026 + hw] - mean) * scv + biv;
    }
}

// ---------------------------------------------------------------------------
// Row softmax over 1024
// ---------------------------------------------------------------------------
__global__ void softmax_kernel(float* __restrict__ S)
{
    __shared__ float sh[8];
    size_t row = blockIdx.x;
    float* p = S + row * HWW;
    int t = threadIdx.x;

    float4 v = ((const float4*)p)[t];
    float m = fmaxf(fmaxf(v.x, v.y), fmaxf(v.z, v.w));
    #pragma unroll
    for (int o = 16; o > 0; o >>= 1) m = fmaxf(m, __shfl_xor_sync(0xffffffffu, m, o));
    if ((t & 31) == 0) sh[t >> 5] = m;
    __syncthreads();
    float M = sh[0];
    #pragma unroll
    for (int i = 1; i < 8; i++) M = fmaxf(M, sh[i]);
    __syncthreads();

    v.x = __expf(v.x - M); v.y = __expf(v.y - M);
    v.z = __expf(v.z - M); v.w = __expf(v.w - M);
    float s = v.x + v.y + v.z + v.w;
    #pragma unroll
    for (int o = 16; o > 0; o >>= 1) s += __shfl_xor_sync(0xffffffffu, s, o);
    if ((t & 31) == 0) sh[t >> 5] = s;
    __syncthreads();
    float T = 0.f;
    #pragma unroll
    for (int i = 0; i < 8; i++) T += sh[i];
    float inv = 1.0f / T;

    v.x *= inv; v.y *= inv; v.z *= inv; v.w *= inv;
    ((float4*)p)[t] = v;
}

// ---------------------------------------------------------------------------
extern "C" void kernel_launch(void* const* d_in, const int* in_sizes, int n_in,
                              void* d_out, int out_size)
{
    const float* x   = (const float*)d_in[0];
    const float* y   = (const float*)d_in[1];
    const float* ns  = (const float*)d_in[2];
    const float* nb  = (const float*)d_in[3];
    const float* n1s = (const float*)d_in[4];
    const float* n1b = (const float*)d_in[5];
    const float* wq  = (const float*)d_in[6];
    const float* bq  = (const float*)d_in[7];
    const float* wk  = (const float*)d_in[8];
    const float* bk  = (const float*)d_in[9];
    const float* wv  = (const float*)d_in[10];
    const float* bv  = (const float*)d_in[11];
    const float* wp  = (const float*)d_in[12];
    const float* bp  = (const float*)d_in[13];
    float* out = (float*)d_out;

    float *hxT, *hyT, *qT, *kT, *v2, *s;
    cudaGetSymbolAddress((void**)&hxT, g_hxT);
    cudaGetSymbolAddress((void**)&hyT, g_hyT);
    cudaGetSymbolAddress((void**)&qT,  g_qT);
    cudaGetSymbolAddress((void**)&kT,  g_kT);
    cudaGetSymbolAddress((void**)&v2,  g_v2);
    cudaGetSymbolAddress((void**)&s,   g_s);
    float* O = hxT;   // hxT dead after k,v GEMMs

    const int SMEM_GEMM = 3 * 2 * 128 * 32 * 4;      // 98304 B
    const int SMEM_GN   = 16 * 1026 * sizeof(float); // 65664 B
    cudaFuncSetAttribute(mma_gemm<0>, cudaFuncAttributeMaxDynamicSharedMemorySize, SMEM_GEMM);
    cudaFuncSetAttribute(mma_gemm<1>, cudaFuncAttributeMaxDynamicSharedMemorySize, SMEM_GEMM);
    cudaFuncSetAttribute(mma_gemm<2>, cudaFuncAttributeMaxDynamicSharedMemorySize, SMEM_GEMM);
    cudaFuncSetAttribute(mma_gemm<3>, cudaFuncAttributeMaxDynamicSharedMemorySize, SMEM_GEMM);
    cudaFuncSetAttribute(mma_gemm<4>, cudaFuncAttributeMaxDynamicSharedMemorySize, SMEM_GEMM);
    cudaFuncSetAttribute(gn_t_kernel, cudaFuncAttributeMaxDynamicSharedMemorySize, SMEM_GN);

    const long AS = (long)CC * HWW;
    const long SS = (long)HWW * HWW;
    const float qkscale = 0.044194173824159216f;   // 512^-0.5

    gn_t_kernel<<<BB * 32, 256, SMEM_GN>>>(x, ns,  nb,  hxT);
    gn_t_kernel<<<BB * 32, 256, SMEM_GN>>>(y, n1s, n1b, hyT);

    // q/k: D[hw, oc] = sum_c actT[hw,c] * W[oc,c] + b[oc]
    dim3 gqkv(CC / 128, HWW / 128, BB);   // (4, 8, 16)
    mma_gemm<0><<<gqkv, 128, SMEM_GEMM>>>(hyT, wq, qT, bq, nullptr, 16, CC, CC, CC, AS, 0, AS, 0.f);
    mma_gemm<0><<<gqkv, 128, SMEM_GEMM>>>(hxT, wk, kT, bk, nullptr, 16, CC, CC, CC, AS, 0, AS, 0.f);
    // v: same GEMM but transposed store -> v2[c][hw] directly (EPI=4, ldc=HWW)
    mma_gemm<4><<<gqkv, 128, SMEM_GEMM>>>(hxT, wv, v2, bv, nullptr, 16, CC, CC, HWW, AS, 0, AS, 0.f);

    // scores: S[i,j] = scale * sum_c qT[i,c] * kT[j,c]
    dim3 gqk(HWW / 128, HWW / 128, BB);   // (8, 8, 16)
    mma_gemm<1><<<gqk, 128, SMEM_GEMM>>>(qT, kT, s, nullptr, nullptr, 16, CC, CC, HWW, AS, AS, SS, qkscale);

    softmax_kernel<<<BB * HWW, 256>>>(s);

    // O[i, c] = sum_j attn[i,j] * v2[c,j]
    dim3 gav(CC / 128, HWW / 128, BB);    // (4, 8, 16)
    mma_gemm<2><<<gav, 128, SMEM_GEMM>>>(s, v2, O, nullptr, nullptr, 32, HWW, HWW, CC, SS, AS, AS, 0.f);

    // out[oc, hw] = sum_c wp[oc,c] * O[hw,c] + bp[oc] + x
    dim3 gproj(HWW / 128, CC / 128, BB);  // (8, 4, 16)
    mma_gemm<3><<<gproj, 128, SMEM_GEMM>>>(wp, O, out, bp, x, 16, CC, CC, HWW, 0, AS, AS, 0.f);
}

// round 11
// speedup vs baseline: 1.4847x; 1.0313x over previous
#include <cuda_runtime.h>
#include <cstdint>
#include <math.h>

#define BB   16
#define CC   512
#define HWW  1024
#define ABUF ((size_t)BB*CC*HWW)      // 8M floats = 32MB

// Scratch (__device__ globals; no allocs allowed)
__device__ float g_hxT[ABUF];   // normalized x, [b][hw][c]; reused as O after k,v
__device__ float g_hyT[ABUF];   // normalized y, [b][hw][c]
__device__ float g_qT [ABUF];   // [b][hw][c]
__device__ float g_kT [ABUF];   // [b][hw][c]
__device__ float g_v2 [ABUF];   // [b][c][hw]  (written directly by V GEMM, EPI=4)
__device__ float g_s  [(size_t)BB*HWW*HWW];  // 64MB scores

__device__ __forceinline__ uint32_t smem_u32(const void* p) {
    uint32_t a;
    asm("{ .reg .u64 t; cvta.to.shared.u64 t, %1; cvt.u32.u64 %0, t; }" : "=r"(a) : "l"(p));
    return a;
}
#define CP_ASYNC16(sa, ga) \
    asm volatile("cp.async.cg.shared.global [%0], [%1], 16;" :: "r"(sa), "l"(ga) : "memory")
#define CP_COMMIT() asm volatile("cp.async.commit_group;" ::: "memory")
#define CP_WAIT1()  asm volatile("cp.async.wait_group 1;" ::: "memory")
#define CP_WAIT0()  asm volatile("cp.async.wait_group 0;" ::: "memory")

__device__ __forceinline__ void ldsm4(uint32_t& r0, uint32_t& r1, uint32_t& r2,
                                      uint32_t& r3, uint32_t addr) {
    asm volatile("ldmatrix.sync.aligned.m8n8.x4.shared.b16 {%0,%1,%2,%3}, [%4];"
                 : "=r"(r0), "=r"(r1), "=r"(r2), "=r"(r3) : "r"(addr));
}

// ---------------------------------------------------------------------------
// tf32 mma.sync GEMM: D[m,n] = sum_k A[m,k]*B[n,k]; 128x128 block tile.
// 3-stage cp.async pipeline (K-chunk 32), ONE __syncthreads per chunk.
// 4 warps, warp tile 64x64 (4x8 m16n8k8), register double-buffered fragments
// loaded via ldmatrix.x4 (tf32-as-b16 trick): 8 LDSM replace 32 scalar LDS
// per 8-K step. XOR-chunk swizzle keeps every ldmatrix phase conflict-free
// (slots C^(row&7) span all eight 16B columns).
// EPI: 0=+bias[n] | 1=*scale | 2=none | 3=+bias[m]+resid
//      4=+bias[n] then TRANSPOSED store via smem (D[m][n] -> C[n][m])
// ---------------------------------------------------------------------------
template<int EPI>
__global__ __launch_bounds__(128, 2)
void mma_gemm(const float* __restrict__ A, const float* __restrict__ B,
              float* __restrict__ C, const float* __restrict__ bias,
              const float* __restrict__ resid,
              int NC, int lda, int ldb, int ldc,
              long aB, long bB, long cB, float scale)
{
    extern __shared__ float sm[];    // 3 stages x (A 128*32 + B 128*32) = 98304 B
    const int TP = 32, TILE = 128 * TP, STG = 2 * TILE;   // floats

    int t = threadIdx.x, lane = t & 31, w = t >> 5;
    int wr = w & 1, wc = w >> 1;          // warp grid 2 x 2, warp tile 64x64
    int g = lane >> 2, tg = lane & 3;
    int bz = blockIdx.z, m0 = blockIdx.y * 128, n0 = blockIdx.x * 128;
    const float* Ab = A + (size_t)bz * aB;
    const float* Bb = B + (size_t)bz * bB;
    float*       Cb = C + (size_t)bz * cB;
    uint32_t smb = smem_u32(sm);

    // ldmatrix per-lane addressing (constant across chunks):
    //  A x4: m0/m1 = rows {g, g+8} chunk lo; m2/m3 = same rows chunk hi
    //    lanes 0-15 -> chunk lo, rows lane&15 ; lanes 16-31 -> chunk hi
    //  B x4: m0/m1 = rows j-block, chunks {lo, hi}; m2/m3 = rows +8
    int lo7 = lane & 7;
    int hiA = lane >> 4;                              // 0..1: chunk select
    int hiB = (lane >> 3) & 1;                        // 0..1: chunk select
    uint32_t rowA_off = (uint32_t)((wr * 64 + (lane & 15)) * TP) * 4u;
    uint32_t rowB_off = (uint32_t)((wc * 64 + lo7 + ((lane & 16) >> 1)) * TP) * 4u;

    auto load = [&](int c, int s) {
        int k0 = c * 32;
        #pragma unroll
        for (int j = 0; j < 8; j++) {
            int idx = t + 128 * j;          // 0..1023
            int r = idx >> 3, cq = idx & 7;
            int cs = cq ^ (r & 7);          // swizzled chunk slot
            const float* ga = Ab + (size_t)(m0 + r) * lda + k0 + cq * 4;
            const float* gb = Bb + (size_t)(n0 + r) * ldb + k0 + cq * 4;
            uint32_t so = (uint32_t)(s * STG + r * TP + cs * 4) * 4u;
            CP_ASYNC16(smb + so, ga);
            CP_ASYNC16(smb + (uint32_t)(TILE * 4) + so, gb);
        }
    };

    float acc[4][8][4];
    #pragma unroll
    for (int i = 0; i < 4; i++)
        #pragma unroll
        for (int j = 0; j < 8; j++)
            #pragma unroll
            for (int q = 0; q < 4; q++) acc[i][j][q] = 0.f;

    // Fragment load via ldmatrix: aBase/bBase are smem byte addrs of the stage.
    auto ldfrag = [&](uint32_t aBase, uint32_t bBase, int s8,
                      uint32_t (&af)[4][4], uint32_t (&bf)[8][2]) {
        uint32_t slA = (uint32_t)(((2 * s8 + hiA) ^ lo7) << 4);
        uint32_t slB = (uint32_t)(((2 * s8 + hiB) ^ lo7) << 4);
        uint32_t aAddr = aBase + rowA_off + slA;
        uint32_t bAddr = bBase + rowB_off + slB;
        #pragma unroll
        for (int i = 0; i < 4; i++)
            ldsm4(af[i][0], af[i][1], af[i][2], af[i][3],
                  aAddr + (uint32_t)(i * 16 * TP) * 4u);
        #pragma unroll
        for (int p = 0; p < 4; p++)
            ldsm4(bf[2 * p][0], bf[2 * p][1], bf[2 * p + 1][0], bf[2 * p + 1][1],
                  bAddr + (uint32_t)(p * 16 * TP) * 4u);
    };

    load(0, 0); CP_COMMIT();
    if (NC > 1) { load(1, 1); CP_COMMIT(); }

    uint32_t af[2][4][4], bf[2][8][2];

    for (int c = 0; c < NC; c++) {
        if (c + 1 < NC) CP_WAIT1(); else CP_WAIT0();   // stage c landed (own groups)
        __syncthreads();                                // cross-thread visibility
        uint32_t aBase = smb + (uint32_t)((c % 3) * STG) * 4u;
        uint32_t bBase = aBase + (uint32_t)(TILE) * 4u;
        ldfrag(aBase, bBase, 0, af[0], bf[0]);          // start LDSM chains first
        if (c + 2 < NC) { load(c + 2, (c + 2) % 3); CP_COMMIT(); }  // hides frag latency

        #pragma unroll
        for (int s8 = 0; s8 < 4; s8++) {
            if (s8 < 3) ldfrag(aBase, bBase, s8 + 1, af[(s8 + 1) & 1], bf[(s8 + 1) & 1]);
            uint32_t (&a)[4][4] = af[s8 & 1];
            uint32_t (&b)[8][2] = bf[s8 & 1];
            #pragma unroll
            for (int i = 0; i < 4; i++)
                #pragma unroll
                for (int j = 0; j < 8; j++)
                    asm volatile(
                        "mma.sync.aligned.m16n8k8.row.col.f32.tf32.tf32.f32 "
                        "{%0,%1,%2,%3},{%4,%5,%6,%7},{%8,%9},{%0,%1,%2,%3};"
                        : "+f"(acc[i][j][0]), "+f"(acc[i][j][1]),
                          "+f"(acc[i][j][2]), "+f"(acc[i][j][3])
                        : "r"(a[i][0]), "r"(a[i][1]), "r"(a[i][2]), "r"(a[i][3]),
                          "r"(b[j][0]), "r"(b[j][1]));
        }
    }

    int mrow = m0 + wr * 64;
    int ncol = n0 + wc * 64;

    if (EPI == 4) {
        // +bias[n], then transposed store: D[m][n] -> C[n][m] via smem staging.
        __syncthreads();                  // all warps done with mainloop smem
        #pragma unroll
        for (int i = 0; i < 4; i++) {
            int rl0 = wr * 64 + i * 16 + g, rl1 = rl0 + 8;
            #pragma unroll
            for (int j = 0; j < 8; j++) {
                int nl = wc * 64 + j * 8 + 2 * tg;
                float b0 = __ldg(&bias[n0 + nl]), b1 = __ldg(&bias[n0 + nl + 1]);
                sm[(nl + 0) * 129 + rl0] = acc[i][j][0] + b0;
                sm[(nl + 1) * 129 + rl0] = acc[i][j][1] + b1;
                sm[(nl + 0) * 129 + rl1] = acc[i][j][2] + b0;
                sm[(nl + 1) * 129 + rl1] = acc[i][j][3] + b1;
            }
        }
        __syncthreads();
        #pragma unroll 4
        for (int rr = 0; rr < 32; rr++) {
            int rloc = w * 32 + rr;
            float* dst = Cb + (size_t)(n0 + rloc) * ldc + m0;
            const float* srcr = sm + rloc * 129;
            #pragma unroll
            for (int k2 = 0; k2 < 4; k2++)
                dst[lane + 32 * k2] = srcr[lane + 32 * k2];
        }
        return;
    }

    #pragma unroll
    for (int i = 0; i < 4; i++) {
        int r0 = mrow + i * 16 + g, r1 = r0 + 8;
        float bm0 = 0.f, bm1 = 0.f;
        if (EPI == 3) { bm0 = __ldg(&bias[r0]); bm1 = __ldg(&bias[r1]); }
        #pragma unroll
        for (int j = 0; j < 8; j++) {
            int cc = ncol + j * 8 + 2 * tg;
            float2 v0 = make_float2(acc[i][j][0], acc[i][j][1]);
            float2 v1 = make_float2(acc[i][j][2], acc[i][j][3]);
            if (EPI == 0) {
                float b0 = __ldg(&bias[cc]), b1 = __ldg(&bias[cc + 1]);
                v0.x += b0; v0.y += b1; v1.x += b0; v1.y += b1;
            } else if (EPI == 1) {
                v0.x *= scale; v0.y *= scale; v1.x *= scale; v1.y *= scale;
            } else if (EPI == 3) {
                const float* Rb = resid + (size_t)bz * cB;
                float2 x0 = *(const float2*)(Rb + (size_t)r0 * ldc + cc);
                float2 x1 = *(const float2*)(Rb + (size_t)r1 * ldc + cc);
                v0.x += bm0 + x0.x; v0.y += bm0 + x0.y;
                v1.x += bm1 + x1.x; v1.y += bm1 + x1.y;
            }
            *(float2*)(Cb + (size_t)r0 * ldc + cc) = v0;
            *(float2*)(Cb + (size_t)r1 * ldc + cc) = v1;
        }
    }
}

// ---------------------------------------------------------------------------
// GroupNorm with transposed output [b][hw][c]. One block per (b, group).
// ---------------------------------------------------------------------------
__global__ void gn_t_kernel(const float* __restrict__ x, const float* __restrict__ sc,
                            const float* __restrict__ bi, float* __restrict__ outT)
{
    extern __shared__ float xs[];      // 16 * 1026
    __shared__ float shs[8], shq[8], shm[2];
    int bg = blockIdx.x;
    int b = bg >> 5, g = bg & 31;
    const float* xp = x + ((size_t)b * CC + (size_t)g * 16) * HWW;
    int t = threadIdx.x;

    float s = 0.f, sq = 0.f;
    #pragma unroll 4
    for (int j = 0; j < 64; j++) {
        int idx = t + 256 * j;               // idx = c*1024 + hw
        float v = xp[idx];
        xs[(idx >> 10) * 1026 + (idx & 1023)] = v;
        s += v; sq += v * v;
    }
    #pragma unroll
    for (int o = 16; o > 0; o >>= 1) {
        s  += __shfl_xor_sync(0xffffffffu, s,  o);
        sq += __shfl_xor_sync(0xffffffffu, sq, o);
    }
    if ((t & 31) == 0) { shs[t >> 5] = s; shq[t >> 5] = sq; }
    __syncthreads();
    if (t == 0) {
        float S = 0.f, Q = 0.f;
        #pragma unroll
        for (int i = 0; i < 8; i++) { S += shs[i]; Q += shq[i]; }
        float mean = S * (1.f / 16384.f);
        float var  = Q * (1.f / 16384.f) - mean * mean;
        shm[0] = mean;
        shm[1] = rsqrtf(var + 1e-6f);
    }
    __syncthreads();
    float mean = shm[0], rs = shm[1];
    int cl = t & 15;
    float scv = __ldg(&sc[g * 16 + cl]) * rs;
    float biv = __ldg(&bi[g * 16 + cl]);
    float* op = outT + (size_t)b * HWW * CC + g * 16;
    #pragma unroll 4
    for (int j = 0; j < 64; j++) {
        int idx = t + 256 * j;
        int hw = idx >> 4;
        op[(size_t)hw * CC + cl] = (xs[cl * 1026 + hw] - mean) * scv + biv;
    }
}

// ---------------------------------------------------------------------------
// Row softmax over 1024
// ---------------------------------------------------------------------------
__global__ void softmax_kernel(float* __restrict__ S)
{
    __shared__ float sh[8];
    size_t row = blockIdx.x;
    float* p = S + row * HWW;
    int t = threadIdx.x;

    float4 v = ((const float4*)p)[t];
    float m = fmaxf(fmaxf(v.x, v.y), fmaxf(v.z, v.w));
    #pragma unroll
    for (int o = 16; o > 0; o >>= 1) m = fmaxf(m, __shfl_xor_sync(0xffffffffu, m, o));
    if ((t & 31) == 0) sh[t >> 5] = m;
    __syncthreads();
    float M = sh[0];
    #pragma unroll
    for (int i = 1; i < 8; i++) M = fmaxf(M, sh[i]);
    __syncthreads();

    v.x = __expf(v.x - M); v.y = __expf(v.y - M);
    v.z = __expf(v.z - M); v.w = __expf(v.w - M);
    float s = v.x + v.y + v.z + v.w;
    #pragma unroll
    for (int o = 16; o > 0; o >>= 1) s += __shfl_xor_sync(0xffffffffu, s, o);
    if ((t & 31) == 0) sh[t >> 5] = s;
    __syncthreads();
    float T = 0.f;
    #pragma unroll
    for (int i = 0; i < 8; i++) T += sh[i];
    float inv = 1.0f / T;

    v.x *= inv; v.y *= inv; v.z *= inv; v.w *= inv;
    ((float4*)p)[t] = v;
}

// ---------------------------------------------------------------------------
extern "C" void kernel_launch(void* const* d_in, const int* in_sizes, int n_in,
                              void* d_out, int out_size)
{
    const float* x   = (const float*)d_in[0];
    const float* y   = (const float*)d_in[1];
    const float* ns  = (const float*)d_in[2];
    const float* nb  = (const float*)d_in[3];
    const float* n1s = (const float*)d_in[4];
    const float* n1b = (const float*)d_in[5];
    const float* wq  = (const float*)d_in[6];
    const float* bq  = (const float*)d_in[7];
    const float* wk  = (const float*)d_in[8];
    const float* bk  = (const float*)d_in[9];
    const float* wv  = (const float*)d_in[10];
    const float* bv  = (const float*)d_in[11];
    const float* wp  = (const float*)d_in[12];
    const float* bp  = (const float*)d_in[13];
    float* out = (float*)d_out;

    float *hxT, *hyT, *qT, *kT, *v2, *s;
    cudaGetSymbolAddress((void**)&hxT, g_hxT);
    cudaGetSymbolAddress((void**)&hyT, g_hyT);
    cudaGetSymbolAddress((void**)&qT,  g_qT);
    cudaGetSymbolAddress((void**)&kT,  g_kT);
    cudaGetSymbolAddress((void**)&v2,  g_v2);
    cudaGetSymbolAddress((void**)&s,   g_s);
    float* O = hxT;   // hxT dead after k,v GEMMs

    const int SMEM_GEMM = 3 * 2 * 128 * 32 * 4;      // 98304 B
    const int SMEM_GN   = 16 * 1026 * sizeof(float); // 65664 B
    cudaFuncSetAttribute(mma_gemm<0>, cudaFuncAttributeMaxDynamicSharedMemorySize, SMEM_GEMM);
    cudaFuncSetAttribute(mma_gemm<1>, cudaFuncAttributeMaxDynamicSharedMemorySize, SMEM_GEMM);
    cudaFuncSetAttribute(mma_gemm<2>, cudaFuncAttributeMaxDynamicSharedMemorySize, SMEM_GEMM);
    cudaFuncSetAttribute(mma_gemm<3>, cudaFuncAttributeMaxDynamicSharedMemorySize, SMEM_GEMM);
    cudaFuncSetAttribute(mma_gemm<4>, cudaFuncAttributeMaxDynamicSharedMemorySize, SMEM_GEMM);
    cudaFuncSetAttribute(gn_t_kernel, cudaFuncAttributeMaxDynamicSharedMemorySize, SMEM_GN);

    const long AS = (long)CC * HWW;
    const long SS = (long)HWW * HWW;
    const float qkscale = 0.044194173824159216f;   // 512^-0.5

    gn_t_kernel<<<BB * 32, 256, SMEM_GN>>>(x, ns,  nb,  hxT);
    gn_t_kernel<<<BB * 32, 256, SMEM_GN>>>(y, n1s, n1b, hyT);

    // q/k: D[hw, oc] = sum_c actT[hw,c] * W[oc,c] + b[oc]
    dim3 gqkv(CC / 128, HWW / 128, BB);   // (4, 8, 16)
    mma_gemm<0><<<gqkv, 128, SMEM_GEMM>>>(hyT, wq, qT, bq, nullptr, 16, CC, CC, CC, AS, 0, AS, 0.f);
    mma_gemm<0><<<gqkv, 128, SMEM_GEMM>>>(hxT, wk, kT, bk, nullptr, 16, CC, CC, CC, AS, 0, AS, 0.f);
    // v: same GEMM but transposed store -> v2[c][hw] directly (EPI=4, ldc=HWW)
    mma_gemm<4><<<gqkv, 128, SMEM_GEMM>>>(hxT, wv, v2, bv, nullptr, 16, CC, CC, HWW, AS, 0, AS, 0.f);

    // scores: S[i,j] = scale * sum_c qT[i,c] * kT[j,c]
    dim3 gqk(HWW / 128, HWW / 128, BB);   // (8, 8, 16)
    mma_gemm<1><<<gqk, 128, SMEM_GEMM>>>(qT, kT, s, nullptr, nullptr, 16, CC, CC, HWW, AS, AS, SS, qkscale);

    softmax_kernel<<<BB * HWW, 256>>>(s);

    // O[i, c] = sum_j attn[i,j] * v2[c,j]
    dim3 gav(CC / 128, HWW / 128, BB);    // (4, 8, 16)
    mma_gemm<2><<<gav, 128, SMEM_GEMM>>>(s, v2, O, nullptr, nullptr, 32, HWW, HWW, CC, SS, AS, AS, 0.f);

    // out[oc, hw] = sum_c wp[oc,c] * O[hw,c] + bp[oc] + x
    dim3 gproj(HWW / 128, CC / 128, BB);  // (8, 4, 16)
    mma_gemm<3><<<gproj, 128, SMEM_GEMM>>>(wp, O, out, bp, x, 16, CC, CC, HWW, 0, AS, AS, 0.f);
}

// round 12
// speedup vs baseline: 2.2269x; 1.4999x over previous
#include <cuda_runtime.h>
#include <cuda_fp16.h>
#include <cstdint>
#include <math.h>

#define BB   16
#define CC   512
#define HWW  1024
#define ABUF ((size_t)BB*CC*HWW)      // 8M elements

// Scratch (__device__ globals; no allocs allowed)
__device__ __half g_hxT[ABUF];   // normalized x, [b][hw][c] fp16; reused as O
__device__ __half g_hyT[ABUF];   // normalized y, [b][hw][c] fp16
__device__ __half g_qT [ABUF];   // [b][hw][c]
__device__ __half g_kT [ABUF];   // [b][hw][c]
__device__ __half g_v2 [ABUF];   // [b][c][hw]
__device__ __half g_wh [4*(size_t)CC*CC];       // fp16 weights: q,k,v,p
__device__ float  g_s  [(size_t)BB*HWW*HWW];    // fp32 scores
__device__ __half g_sh [(size_t)BB*HWW*HWW];    // fp16 probs

__device__ __forceinline__ uint32_t smem_u32(const void* p) {
    uint32_t a;
    asm("{ .reg .u64 t; cvta.to.shared.u64 t, %1; cvt.u32.u64 %0, t; }" : "=r"(a) : "l"(p));
    return a;
}
#define CP_ASYNC16(sa, ga) \
    asm volatile("cp.async.cg.shared.global [%0], [%1], 16;" :: "r"(sa), "l"(ga) : "memory")
#define CP_COMMIT() asm volatile("cp.async.commit_group;" ::: "memory")
#define CP_WAIT1()  asm volatile("cp.async.wait_group 1;" ::: "memory")
#define CP_WAIT0()  asm volatile("cp.async.wait_group 0;" ::: "memory")

__device__ __forceinline__ void ldsm4(uint32_t& r0, uint32_t& r1, uint32_t& r2,
                                      uint32_t& r3, uint32_t addr) {
    asm volatile("ldmatrix.sync.aligned.m8n8.x4.shared.b16 {%0,%1,%2,%3}, [%4];"
                 : "=r"(r0), "=r"(r1), "=r"(r2), "=r"(r3) : "r"(addr));
}

// ---------------------------------------------------------------------------
// fp16 mma.sync GEMM (f32 accum): D[m,n] = sum_k A[m,k]*B[n,k]; 128x128 tile.
// 3-stage cp.async pipeline, K-chunk 64 halves (128B/row, 8x16B chunks, XOR
// swizzle chunk^(row&7)), ONE barrier per chunk. 4 warps, warp tile 64x64 =
// 4x8 m16n8k16, ldmatrix.x4 fragments, register double-buffered k16-steps.
// EPI: 0=+bias[n]->half | 1=*scale->f32 | 2=none->half | 3=+bias[m]+resid->f32
//      4=+bias[n], TRANSPOSED half store (D[m][n] -> C[n][m])
// ---------------------------------------------------------------------------
template<int EPI>
__global__ __launch_bounds__(128, 2)
void mma_gemm(const __half* __restrict__ A, const __half* __restrict__ B,
              void* __restrict__ Cv, const float* __restrict__ bias,
              const float* __restrict__ resid,
              int NC, int lda, int ldb, int ldc,
              long aB, long bB, long cB, float scale)
{
    extern __shared__ float sm[];    // 3 stages x (A 16KB + B 16KB) = 96 KB
    const int TILEB = 128 * 128, STGB = 2 * TILEB;   // bytes

    int t = threadIdx.x, lane = t & 31, w = t >> 5;
    int wr = w & 1, wc = w >> 1;          // warp grid 2x2, warp tile 64x64
    int g = lane >> 2, tg = lane & 3;
    int lo7 = lane & 7;
    int hiA = lane >> 4;                  // A: byte-block select (0/1)
    int hiB = (lane >> 3) & 1;            // B: byte-block select (0/1)
    int bz = blockIdx.z, m0 = blockIdx.y * 128, n0 = blockIdx.x * 128;
    const __half* Ab = A + (size_t)bz * aB;
    const __half* Bb = B + (size_t)bz * bB;
    uint32_t smb = smem_u32(sm);

    uint32_t rowA_off = (uint32_t)((wr * 64 + (lane & 15)) * 128);
    uint32_t rowB_off = (uint32_t)((wc * 64 + lo7 + ((lane & 16) >> 1)) * 128);

    auto load = [&](int c, int s) {
        int k0 = c * 64;                  // halves
        #pragma unroll
        for (int j = 0; j < 8; j++) {
            int idx = t + 128 * j;        // 0..1023
            int r = idx >> 3, cq = idx & 7;
            int cs = cq ^ (r & 7);        // swizzled chunk slot
            const __half* ga = Ab + (size_t)(m0 + r) * lda + k0 + cq * 8;
            const __half* gb = Bb + (size_t)(n0 + r) * ldb + k0 + cq * 8;
            uint32_t so = (uint32_t)(s * STGB + r * 128 + cs * 16);
            CP_ASYNC16(smb + so, ga);
            CP_ASYNC16(smb + (uint32_t)TILEB + so, gb);
        }
    };

    float acc[4][8][4];
    #pragma unroll
    for (int i = 0; i < 4; i++)
        #pragma unroll
        for (int j = 0; j < 8; j++)
            #pragma unroll
            for (int q = 0; q < 4; q++) acc[i][j][q] = 0.f;

    // One k16-step: bytes 32*s16..+31 = chunks {2*s16, 2*s16+1}
    auto ldfrag = [&](uint32_t aBase, uint32_t bBase, int s16,
                      uint32_t (&af)[4][4], uint32_t (&bf)[8][2]) {
        uint32_t slA = (uint32_t)(((2 * s16 + hiA) ^ lo7) << 4);
        uint32_t slB = (uint32_t)(((2 * s16 + hiB) ^ lo7) << 4);
        uint32_t aAddr = aBase + rowA_off + slA;
        uint32_t bAddr = bBase + rowB_off + slB;
        #pragma unroll
        for (int i = 0; i < 4; i++)
            ldsm4(af[i][0], af[i][1], af[i][2], af[i][3],
                  aAddr + (uint32_t)(i * 16 * 128));
        #pragma unroll
        for (int p = 0; p < 4; p++)
            ldsm4(bf[2 * p][0], bf[2 * p][1], bf[2 * p + 1][0], bf[2 * p + 1][1],
                  bAddr + (uint32_t)(p * 16 * 128));
    };

    load(0, 0); CP_COMMIT();
    if (NC > 1) { load(1, 1); CP_COMMIT(); }

    uint32_t af[2][4][4], bf[2][8][2];

    for (int c = 0; c < NC; c++) {
        if (c + 1 < NC) CP_WAIT1(); else CP_WAIT0();
        __syncthreads();
        uint32_t aBase = smb + (uint32_t)((c % 3) * STGB);
        uint32_t bBase = aBase + (uint32_t)TILEB;
        ldfrag(aBase, bBase, 0, af[0], bf[0]);
        if (c + 2 < NC) { load(c + 2, (c + 2) % 3); CP_COMMIT(); }

        #pragma unroll
        for (int s16 = 0; s16 < 4; s16++) {
            if (s16 < 3) ldfrag(aBase, bBase, s16 + 1, af[(s16 + 1) & 1], bf[(s16 + 1) & 1]);
            uint32_t (&a)[4][4] = af[s16 & 1];
            uint32_t (&b)[8][2] = bf[s16 & 1];
            #pragma unroll
            for (int i = 0; i < 4; i++)
                #pragma unroll
                for (int j = 0; j < 8; j++)
                    asm volatile(
                        "mma.sync.aligned.m16n8k16.row.col.f32.f16.f16.f32 "
                        "{%0,%1,%2,%3},{%4,%5,%6,%7},{%8,%9},{%0,%1,%2,%3};"
                        : "+f"(acc[i][j][0]), "+f"(acc[i][j][1]),
                          "+f"(acc[i][j][2]), "+f"(acc[i][j][3])
                        : "r"(a[i][0]), "r"(a[i][1]), "r"(a[i][2]), "r"(a[i][3]),
                          "r"(b[j][0]), "r"(b[j][1]));
        }
    }

    int mrow = m0 + wr * 64;
    int ncol = n0 + wc * 64;

    if (EPI == 4) {
        // +bias[n], transposed half store via fp32 smem staging (pad 129).
        __half* Cb = (__half*)Cv + (size_t)bz * cB;
        __syncthreads();
        #pragma unroll
        for (int i = 0; i < 4; i++) {
            int rl0 = wr * 64 + i * 16 + g, rl1 = rl0 + 8;
            #pragma unroll
            for (int j = 0; j < 8; j++) {
                int nl = wc * 64 + j * 8 + 2 * tg;
                float b0 = __ldg(&bias[n0 + nl]), b1 = __ldg(&bias[n0 + nl + 1]);
                sm[(nl + 0) * 129 + rl0] = acc[i][j][0] + b0;
                sm[(nl + 1) * 129 + rl0] = acc[i][j][1] + b1;
                sm[(nl + 0) * 129 + rl1] = acc[i][j][2] + b0;
                sm[(nl + 1) * 129 + rl1] = acc[i][j][3] + b1;
            }
        }
        __syncthreads();
        #pragma unroll 4
        for (int rr = 0; rr < 32; rr++) {
            int rloc = w * 32 + rr;
            __half* dst = Cb + (size_t)(n0 + rloc) * ldc + m0;
            const float* srcr = sm + rloc * 129;
            #pragma unroll
            for (int k2 = 0; k2 < 4; k2++)
                dst[lane + 32 * k2] = __float2half_rn(srcr[lane + 32 * k2]);
        }
        return;
    }

    #pragma unroll
    for (int i = 0; i < 4; i++) {
        int r0 = mrow + i * 16 + g, r1 = r0 + 8;
        float bm0 = 0.f, bm1 = 0.f;
        if (EPI == 3) { bm0 = __ldg(&bias[r0]); bm1 = __ldg(&bias[r1]); }
        #pragma unroll
        for (int j = 0; j < 8; j++) {
            int cc = ncol + j * 8 + 2 * tg;
            float2 v0 = make_float2(acc[i][j][0], acc[i][j][1]);
            float2 v1 = make_float2(acc[i][j][2], acc[i][j][3]);
            if (EPI == 0) {
                __half* Cb = (__half*)Cv + (size_t)bz * cB;
                float b0 = __ldg(&bias[cc]), b1 = __ldg(&bias[cc + 1]);
                *(__half2*)(Cb + (size_t)r0 * ldc + cc) = __floats2half2_rn(v0.x + b0, v0.y + b1);
                *(__half2*)(Cb + (size_t)r1 * ldc + cc) = __floats2half2_rn(v1.x + b0, v1.y + b1);
            } else if (EPI == 1) {
                float* Cb = (float*)Cv + (size_t)bz * cB;
                v0.x *= scale; v0.y *= scale; v1.x *= scale; v1.y *= scale;
                *(float2*)(Cb + (size_t)r0 * ldc + cc) = v0;
                *(float2*)(Cb + (size_t)r1 * ldc + cc) = v1;
            } else if (EPI == 2) {
                __half* Cb = (__half*)Cv + (size_t)bz * cB;
                *(__half2*)(Cb + (size_t)r0 * ldc + cc) = __floats2half2_rn(v0.x, v0.y);
                *(__half2*)(Cb + (size_t)r1 * ldc + cc) = __floats2half2_rn(v1.x, v1.y);
            } else {
                float* Cb = (float*)Cv + (size_t)bz * cB;
                const float* Rb = resid + (size_t)bz * cB;
                float2 x0 = *(const float2*)(Rb + (size_t)r0 * ldc + cc);
                float2 x1 = *(const float2*)(Rb + (size_t)r1 * ldc + cc);
                v0.x += bm0 + x0.x; v0.y += bm0 + x0.y;
                v1.x += bm1 + x1.x; v1.y += bm1 + x1.y;
                *(float2*)(Cb + (size_t)r0 * ldc + cc) = v0;
                *(float2*)(Cb + (size_t)r1 * ldc + cc) = v1;
            }
        }
    }
}

// ---------------------------------------------------------------------------
// fp32 -> fp16 conversion (weights)
// ---------------------------------------------------------------------------
__global__ void cvt_half_kernel(const float* __restrict__ src, __half* __restrict__ dst)
{
    int i = (blockIdx.x * blockDim.x + threadIdx.x) * 4;
    float4 v = *(const float4*)(src + i);
    __half2* d = (__half2*)(dst + i);
    d[0] = __floats2half2_rn(v.x, v.y);
    d[1] = __floats2half2_rn(v.z, v.w);
}

// ---------------------------------------------------------------------------
// GroupNorm with transposed fp16 output [b][hw][c]. One block per (b, group).
// ---------------------------------------------------------------------------
__global__ void gn_t_kernel(const float* __restrict__ x, const float* __restrict__ sc,
                            const float* __restrict__ bi, __half* __restrict__ outT)
{
    extern __shared__ float xs[];      // 16 * 1026
    __shared__ float shs[8], shq[8], shm[2];
    int bg = blockIdx.x;
    int b = bg >> 5, g = bg & 31;
    const float* xp = x + ((size_t)b * CC + (size_t)g * 16) * HWW;
    int t = threadIdx.x;

    float s = 0.f, sq = 0.f;
    #pragma unroll 4
    for (int j = 0; j < 64; j++) {
        int idx = t + 256 * j;               // idx = c*1024 + hw
        float v = xp[idx];
        xs[(idx >> 10) * 1026 + (idx & 1023)] = v;
        s += v; sq += v * v;
    }
    #pragma unroll
    for (int o = 16; o > 0; o >>= 1) {
        s  += __shfl_xor_sync(0xffffffffu, s,  o);
        sq += __shfl_xor_sync(0xffffffffu, sq, o);
    }
    if ((t & 31) == 0) { shs[t >> 5] = s; shq[t >> 5] = sq; }
    __syncthreads();
    if (t == 0) {
        float S = 0.f, Q = 0.f;
        #pragma unroll
        for (int i = 0; i < 8; i++) { S += shs[i]; Q += shq[i]; }
        float mean = S * (1.f / 16384.f);
        float var  = Q * (1.f / 16384.f) - mean * mean;
        shm[0] = mean;
        shm[1] = rsqrtf(var + 1e-6f);
    }
    __syncthreads();
    float mean = shm[0], rs = shm[1];
    int cl = t & 15;
    float scv = __ldg(&sc[g * 16 + cl]) * rs;
    float biv = __ldg(&bi[g * 16 + cl]);
    __half* op = outT + (size_t)b * HWW * CC + g * 16;
    #pragma unroll 4
    for (int j = 0; j < 64; j++) {
        int idx = t + 256 * j;
        int hw = idx >> 4;
        op[(size_t)hw * CC + cl] = __float2half_rn((xs[cl * 1026 + hw] - mean) * scv + biv);
    }
}

// ---------------------------------------------------------------------------
// Row softmax over 1024: read fp32 scores, write fp16 probs
// ---------------------------------------------------------------------------
__global__ void softmax_kernel(const float* __restrict__ S, __half* __restrict__ Sh)
{
    __shared__ float sh[8];
    size_t row = blockIdx.x;
    const float* p = S + row * HWW;
    int t = threadIdx.x;

    float4 v = ((const float4*)p)[t];
    float m = fmaxf(fmaxf(v.x, v.y), fmaxf(v.z, v.w));
    #pragma unroll
    for (int o = 16; o > 0; o >>= 1) m = fmaxf(m, __shfl_xor_sync(0xffffffffu, m, o));
    if ((t & 31) == 0) sh[t >> 5] = m;
    __syncthreads();
    float M = sh[0];
    #pragma unroll
    for (int i = 1; i < 8; i++) M = fmaxf(M, sh[i]);
    __syncthreads();

    v.x = __expf(v.x - M); v.y = __expf(v.y - M);
    v.z = __expf(v.z - M); v.w = __expf(v.w - M);
    float s = v.x + v.y + v.z + v.w;
    #pragma unroll
    for (int o = 16; o > 0; o >>= 1) s += __shfl_xor_sync(0xffffffffu, s, o);
    if ((t & 31) == 0) sh[t >> 5] = s;
    __syncthreads();
    float T = 0.f;
    #pragma unroll
    for (int i = 0; i < 8; i++) T += sh[i];
    float inv = 1.0f / T;

    __half2* ph = (__half2*)(Sh + row * HWW);
    ph[2 * t + 0] = __floats2half2_rn(v.x * inv, v.y * inv);
    ph[2 * t + 1] = __floats2half2_rn(v.z * inv, v.w * inv);
}

// ---------------------------------------------------------------------------
extern "C" void kernel_launch(void* const* d_in, const int* in_sizes, int n_in,
                              void* d_out, int out_size)
{
    const float* x   = (const float*)d_in[0];
    const float* y   = (const float*)d_in[1];
    const float* ns  = (const float*)d_in[2];
    const float* nb  = (const float*)d_in[3];
    const float* n1s = (const float*)d_in[4];
    const float* n1b = (const float*)d_in[5];
    const float* wq  = (const float*)d_in[6];
    const float* bq  = (const float*)d_in[7];
    const float* wk  = (const float*)d_in[8];
    const float* bk  = (const float*)d_in[9];
    const float* wv  = (const float*)d_in[10];
    const float* bv  = (const float*)d_in[11];
    const float* wp  = (const float*)d_in[12];
    const float* bp  = (const float*)d_in[13];
    float* out = (float*)d_out;

    __half *hxT, *hyT, *qT, *kT, *v2, *wh, *sh;
    float *s;
    cudaGetSymbolAddress((void**)&hxT, g_hxT);
    cudaGetSymbolAddress((void**)&hyT, g_hyT);
    cudaGetSymbolAddress((void**)&qT,  g_qT);
    cudaGetSymbolAddress((void**)&kT,  g_kT);
    cudaGetSymbolAddress((void**)&v2,  g_v2);
    cudaGetSymbolAddress((void**)&wh,  g_wh);
    cudaGetSymbolAddress((void**)&s,   g_s);
    cudaGetSymbolAddress((void**)&sh,  g_sh);
    __half* O = hxT;   // hxT dead after k,v GEMMs
    __half* whq = wh;
    __half* whk = wh + (size_t)CC * CC;
    __half* whv = wh + 2 * (size_t)CC * CC;
    __half* whp = wh + 3 * (size_t)CC * CC;

    const int SMEM_GEMM = 3 * 2 * 128 * 128;         // 98304 B
    const int SMEM_GN   = 16 * 1026 * sizeof(float); // 65664 B
    cudaFuncSetAttribute(mma_gemm<0>, cudaFuncAttributeMaxDynamicSharedMemorySize, SMEM_GEMM);
    cudaFuncSetAttribute(mma_gemm<1>, cudaFuncAttributeMaxDynamicSharedMemorySize, SMEM_GEMM);
    cudaFuncSetAttribute(mma_gemm<2>, cudaFuncAttributeMaxDynamicSharedMemorySize, SMEM_GEMM);
    cudaFuncSetAttribute(mma_gemm<3>, cudaFuncAttributeMaxDynamicSharedMemorySize, SMEM_GEMM);
    cudaFuncSetAttribute(mma_gemm<4>, cudaFuncAttributeMaxDynamicSharedMemorySize, SMEM_GEMM);
    cudaFuncSetAttribute(gn_t_kernel, cudaFuncAttributeMaxDynamicSharedMemorySize, SMEM_GN);

    const long AS = (long)CC * HWW;
    const long SS = (long)HWW * HWW;
    const float qkscale = 0.044194173824159216f;   // 512^-0.5

    // Weight conversion (1 MB total)
    cvt_half_kernel<<<256, 256>>>(wq, whq);
    cvt_half_kernel<<<256, 256>>>(wk, whk);
    cvt_half_kernel<<<256, 256>>>(wv, whv);
    cvt_half_kernel<<<256, 256>>>(wp, whp);

    gn_t_kernel<<<BB * 32, 256, SMEM_GN>>>(x, ns,  nb,  hxT);
    gn_t_kernel<<<BB * 32, 256, SMEM_GN>>>(y, n1s, n1b, hyT);

    // q/k: D[hw, oc] = sum_c actT[hw,c] * W[oc,c] + b[oc]  (half out)
    dim3 gqkv(CC / 128, HWW / 128, BB);   // (4, 8, 16)
    mma_gemm<0><<<gqkv, 128, SMEM_GEMM>>>(hyT, whq, qT, bq, nullptr, 8, CC, CC, CC, AS, 0, AS, 0.f);
    mma_gemm<0><<<gqkv, 128, SMEM_GEMM>>>(hxT, whk, kT, bk, nullptr, 8, CC, CC, CC, AS, 0, AS, 0.f);
    // v: transposed half store -> v2[c][hw] (EPI=4, ldc=HWW)
    mma_gemm<4><<<gqkv, 128, SMEM_GEMM>>>(hxT, whv, v2, bv, nullptr, 8, CC, CC, HWW, AS, 0, AS, 0.f);

    // scores: S[i,j] = scale * sum_c qT[i,c] * kT[j,c]  (fp32 out)
    dim3 gqk(HWW / 128, HWW / 128, BB);   // (8, 8, 16)
    mma_gemm<1><<<gqk, 128, SMEM_GEMM>>>(qT, kT, s, nullptr, nullptr, 8, CC, CC, HWW, AS, AS, SS, qkscale);

    softmax_kernel<<<BB * HWW, 256>>>(s, sh);

    // O[i, c] = sum_j probs[i,j] * v2[c,j]  (half out)
    dim3 gav(CC / 128, HWW / 128, BB);    // (4, 8, 16)
    mma_gemm<2><<<gav, 128, SMEM_GEMM>>>(sh, v2, O, nullptr, nullptr, 16, HWW, HWW, CC, SS, AS, AS, 0.f);

    // out[oc, hw] = sum_c wp[oc,c] * O[hw,c] + bp[oc] + x  (fp32 out)
    dim3 gproj(HWW / 128, CC / 128, BB);  // (8, 4, 16)
    mma_gemm<3><<<gproj, 128, SMEM_GEMM>>>(whp, O, out, bp, x, 8, CC, CC, HWW, 0, AS, AS, 0.f);
}

// round 13
// speedup vs baseline: 2.3521x; 1.0562x over previous
#include <cuda_runtime.h>
#include <cuda_fp16.h>
#include <cstdint>
#include <math.h>

#define BB   16
#define CC   512
#define HWW  1024
#define ABUF ((size_t)BB*CC*HWW)      // 8M elements

// Scratch (__device__ globals; no allocs allowed)
__device__ __half g_hxT[ABUF];   // normalized x, [b][hw][c] fp16; reused as O
__device__ __half g_hyT[ABUF];   // normalized y, [b][hw][c] fp16
__device__ __half g_qT [ABUF];   // [b][hw][c]
__device__ __half g_kT [ABUF];   // [b][hw][c]
__device__ __half g_v2 [ABUF];   // [b][c][hw]
__device__ __half g_wh [4*(size_t)CC*CC];       // fp16 weights: q,k,v,p
__device__ __half g_sh [(size_t)BB*HWW*HWW];    // fp16 scores -> probs (in-place)

__device__ __forceinline__ uint32_t smem_u32(const void* p) {
    uint32_t a;
    asm("{ .reg .u64 t; cvta.to.shared.u64 t, %1; cvt.u32.u64 %0, t; }" : "=r"(a) : "l"(p));
    return a;
}
#define CP_ASYNC16(sa, ga) \
    asm volatile("cp.async.cg.shared.global [%0], [%1], 16;" :: "r"(sa), "l"(ga) : "memory")
#define CP_COMMIT() asm volatile("cp.async.commit_group;" ::: "memory")
#define CP_WAIT1()  asm volatile("cp.async.wait_group 1;" ::: "memory")
#define CP_WAIT0()  asm volatile("cp.async.wait_group 0;" ::: "memory")

__device__ __forceinline__ void ldsm4(uint32_t& r0, uint32_t& r1, uint32_t& r2,
                                      uint32_t& r3, uint32_t addr) {
    asm volatile("ldmatrix.sync.aligned.m8n8.x4.shared.b16 {%0,%1,%2,%3}, [%4];"
                 : "=r"(r0), "=r"(r1), "=r"(r2), "=r"(r3) : "r"(addr));
}

// ---------------------------------------------------------------------------
// fp16 mma.sync GEMM (f32 accum): D[m,n] = sum_k A[m,k]*B[n,k]; 128x128 tile.
// 3-stage cp.async pipeline, K-chunk 64 halves (128B/row, XOR swizzle), one
// barrier per chunk. 4 warps, warp tile 64x64 = 4x8 m16n8k16, ldmatrix.x4,
// register double-buffered k16-steps.
// EPI: 0=+bias[n]->half | 1=*scale->half | 2=none->half | 3=+bias[m]+resid->f32
//      4=+bias[n], TRANSPOSED half store (D[m][n] -> C[n][m])
// ---------------------------------------------------------------------------
template<int EPI>
__global__ __launch_bounds__(128, 2)
void mma_gemm(const __half* __restrict__ A, const __half* __restrict__ B,
              void* __restrict__ Cv, const float* __restrict__ bias,
              const float* __restrict__ resid,
              int NC, int lda, int ldb, int ldc,
              long aB, long bB, long cB, float scale)
{
    extern __shared__ float sm[];    // 3 stages x (A 16KB + B 16KB) = 96 KB
    const int TILEB = 128 * 128, STGB = 2 * TILEB;   // bytes

    int t = threadIdx.x, lane = t & 31, w = t >> 5;
    int wr = w & 1, wc = w >> 1;          // warp grid 2x2, warp tile 64x64
    int g = lane >> 2, tg = lane & 3;
    int lo7 = lane & 7;
    int hiA = lane >> 4;                  // A: byte-block select (0/1)
    int hiB = (lane >> 3) & 1;            // B: byte-block select (0/1)
    int bz = blockIdx.z, m0 = blockIdx.y * 128, n0 = blockIdx.x * 128;
    const __half* Ab = A + (size_t)bz * aB;
    const __half* Bb = B + (size_t)bz * bB;
    uint32_t smb = smem_u32(sm);

    uint32_t rowA_off = (uint32_t)((wr * 64 + (lane & 15)) * 128);
    uint32_t rowB_off = (uint32_t)((wc * 64 + lo7 + ((lane & 16) >> 1)) * 128);

    auto load = [&](int c, int s) {
        int k0 = c * 64;                  // halves
        #pragma unroll
        for (int j = 0; j < 8; j++) {
            int idx = t + 128 * j;        // 0..1023
            int r = idx >> 3, cq = idx & 7;
            int cs = cq ^ (r & 7);        // swizzled chunk slot
            const __half* ga = Ab + (size_t)(m0 + r) * lda + k0 + cq * 8;
            const __half* gb = Bb + (size_t)(n0 + r) * ldb + k0 + cq * 8;
            uint32_t so = (uint32_t)(s * STGB + r * 128 + cs * 16);
            CP_ASYNC16(smb + so, ga);
            CP_ASYNC16(smb + (uint32_t)TILEB + so, gb);
        }
    };

    float acc[4][8][4];
    #pragma unroll
    for (int i = 0; i < 4; i++)
        #pragma unroll
        for (int j = 0; j < 8; j++)
            #pragma unroll
            for (int q = 0; q < 4; q++) acc[i][j][q] = 0.f;

    auto ldfrag = [&](uint32_t aBase, uint32_t bBase, int s16,
                      uint32_t (&af)[4][4], uint32_t (&bf)[8][2]) {
        uint32_t slA = (uint32_t)(((2 * s16 + hiA) ^ lo7) << 4);
        uint32_t slB = (uint32_t)(((2 * s16 + hiB) ^ lo7) << 4);
        uint32_t aAddr = aBase + rowA_off + slA;
        uint32_t bAddr = bBase + rowB_off + slB;
        #pragma unroll
        for (int i = 0; i < 4; i++)
            ldsm4(af[i][0], af[i][1], af[i][2], af[i][3],
                  aAddr + (uint32_t)(i * 16 * 128));
        #pragma unroll
        for (int p = 0; p < 4; p++)
            ldsm4(bf[2 * p][0], bf[2 * p][1], bf[2 * p + 1][0], bf[2 * p + 1][1],
                  bAddr + (uint32_t)(p * 16 * 128));
    };

    load(0, 0); CP_COMMIT();
    if (NC > 1) { load(1, 1); CP_COMMIT(); }

    uint32_t af[2][4][4], bf[2][8][2];

    for (int c = 0; c < NC; c++) {
        if (c + 1 < NC) CP_WAIT1(); else CP_WAIT0();
        __syncthreads();
        uint32_t aBase = smb + (uint32_t)((c % 3) * STGB);
        uint32_t bBase = aBase + (uint32_t)TILEB;
        ldfrag(aBase, bBase, 0, af[0], bf[0]);
        if (c + 2 < NC) { load(c + 2, (c + 2) % 3); CP_COMMIT(); }

        #pragma unroll
        for (int s16 = 0; s16 < 4; s16++) {
            if (s16 < 3) ldfrag(aBase, bBase, s16 + 1, af[(s16 + 1) & 1], bf[(s16 + 1) & 1]);
            uint32_t (&a)[4][4] = af[s16 & 1];
            uint32_t (&b)[8][2] = bf[s16 & 1];
            #pragma unroll
            for (int i = 0; i < 4; i++)
                #pragma unroll
                for (int j = 0; j < 8; j++)
                    asm volatile(
                        "mma.sync.aligned.m16n8k16.row.col.f32.f16.f16.f32 "
                        "{%0,%1,%2,%3},{%4,%5,%6,%7},{%8,%9},{%0,%1,%2,%3};"
                        : "+f"(acc[i][j][0]), "+f"(acc[i][j][1]),
                          "+f"(acc[i][j][2]), "+f"(acc[i][j][3])
                        : "r"(a[i][0]), "r"(a[i][1]), "r"(a[i][2]), "r"(a[i][3]),
                          "r"(b[j][0]), "r"(b[j][1]));
        }
    }

    int mrow = m0 + wr * 64;
    int ncol = n0 + wc * 64;

    if (EPI == 4) {
        // +bias[n], transposed half store via fp32 smem staging (pad 129).
        __half* Cb = (__half*)Cv + (size_t)bz * cB;
        __syncthreads();
        #pragma unroll
        for (int i = 0; i < 4; i++) {
            int rl0 = wr * 64 + i * 16 + g, rl1 = rl0 + 8;
            #pragma unroll
            for (int j = 0; j < 8; j++) {
                int nl = wc * 64 + j * 8 + 2 * tg;
                float b0 = __ldg(&bias[n0 + nl]), b1 = __ldg(&bias[n0 + nl + 1]);
                sm[(nl + 0) * 129 + rl0] = acc[i][j][0] + b0;
                sm[(nl + 1) * 129 + rl0] = acc[i][j][1] + b1;
                sm[(nl + 0) * 129 + rl1] = acc[i][j][2] + b0;
                sm[(nl + 1) * 129 + rl1] = acc[i][j][3] + b1;
            }
        }
        __syncthreads();
        #pragma unroll 4
        for (int rr = 0; rr < 32; rr++) {
            int rloc = w * 32 + rr;
            __half* dst = Cb + (size_t)(n0 + rloc) * ldc + m0;
            const float* srcr = sm + rloc * 129;
            #pragma unroll
            for (int k2 = 0; k2 < 4; k2++)
                dst[lane + 32 * k2] = __float2half_rn(srcr[lane + 32 * k2]);
        }
        return;
    }

    #pragma unroll
    for (int i = 0; i < 4; i++) {
        int r0 = mrow + i * 16 + g, r1 = r0 + 8;
        float bm0 = 0.f, bm1 = 0.f;
        if (EPI == 3) { bm0 = __ldg(&bias[r0]); bm1 = __ldg(&bias[r1]); }
        #pragma unroll
        for (int j = 0; j < 8; j++) {
            int cc = ncol + j * 8 + 2 * tg;
            float2 v0 = make_float2(acc[i][j][0], acc[i][j][1]);
            float2 v1 = make_float2(acc[i][j][2], acc[i][j][3]);
            if (EPI == 0) {
                __half* Cb = (__half*)Cv + (size_t)bz * cB;
                float b0 = __ldg(&bias[cc]), b1 = __ldg(&bias[cc + 1]);
                *(__half2*)(Cb + (size_t)r0 * ldc + cc) = __floats2half2_rn(v0.x + b0, v0.y + b1);
                *(__half2*)(Cb + (size_t)r1 * ldc + cc) = __floats2half2_rn(v1.x + b0, v1.y + b1);
            } else if (EPI == 1) {
                __half* Cb = (__half*)Cv + (size_t)bz * cB;
                *(__half2*)(Cb + (size_t)r0 * ldc + cc) = __floats2half2_rn(v0.x * scale, v0.y * scale);
                *(__half2*)(Cb + (size_t)r1 * ldc + cc) = __floats2half2_rn(v1.x * scale, v1.y * scale);
            } else if (EPI == 2) {
                __half* Cb = (__half*)Cv + (size_t)bz * cB;
                *(__half2*)(Cb + (size_t)r0 * ldc + cc) = __floats2half2_rn(v0.x, v0.y);
                *(__half2*)(Cb + (size_t)r1 * ldc + cc) = __floats2half2_rn(v1.x, v1.y);
            } else {
                float* Cb = (float*)Cv + (size_t)bz * cB;
                const float* Rb = resid + (size_t)bz * cB;
                float2 x0 = *(const float2*)(Rb + (size_t)r0 * ldc + cc);
                float2 x1 = *(const float2*)(Rb + (size_t)r1 * ldc + cc);
                v0.x += bm0 + x0.x; v0.y += bm0 + x0.y;
                v1.x += bm1 + x1.x; v1.y += bm1 + x1.y;
                *(float2*)(Cb + (size_t)r0 * ldc + cc) = v0;
                *(float2*)(Cb + (size_t)r1 * ldc + cc) = v1;
            }
        }
    }
}

// ---------------------------------------------------------------------------
// fp32 -> fp16 weight conversion, all 4 matrices in ONE launch (grid.y = mat)
// ---------------------------------------------------------------------------
__global__ void cvt_half4_kernel(const float* __restrict__ s0, const float* __restrict__ s1,
                                 const float* __restrict__ s2, const float* __restrict__ s3,
                                 __half* __restrict__ dst)
{
    const float* srcs[4] = {s0, s1, s2, s3};
    const float* src = srcs[blockIdx.y];
    int i = (blockIdx.x * blockDim.x + threadIdx.x) * 4;
    float4 v = *(const float4*)(src + i);
    __half2* d = (__half2*)(dst + (size_t)blockIdx.y * CC * CC + i);
    d[0] = __floats2half2_rn(v.x, v.y);
    d[1] = __floats2half2_rn(v.z, v.w);
}

// ---------------------------------------------------------------------------
// GroupNorm, both tensors in one launch (grid.y selects x/y), fp16 transposed
// output [b][hw][c]. One block per (b, group).
// ---------------------------------------------------------------------------
__global__ void gn_t_kernel(const float* __restrict__ x0, const float* __restrict__ sc0,
                            const float* __restrict__ bi0, __half* __restrict__ o0,
                            const float* __restrict__ x1, const float* __restrict__ sc1,
                            const float* __restrict__ bi1, __half* __restrict__ o1)
{
    extern __shared__ float xs[];      // 16 * 1026
    __shared__ float shs[8], shq[8], shm[2];
    const float* x  = blockIdx.y ? x1  : x0;
    const float* sc = blockIdx.y ? sc1 : sc0;
    const float* bi = blockIdx.y ? bi1 : bi0;
    __half* outT    = blockIdx.y ? o1  : o0;
    int bg = blockIdx.x;
    int b = bg >> 5, g = bg & 31;
    const float* xp = x + ((size_t)b * CC + (size_t)g * 16) * HWW;
    int t = threadIdx.x;

    float s = 0.f, sq = 0.f;
    #pragma unroll 4
    for (int j = 0; j < 64; j++) {
        int idx = t + 256 * j;               // idx = c*1024 + hw
        float v = xp[idx];
        xs[(idx >> 10) * 1026 + (idx & 1023)] = v;
        s += v; sq += v * v;
    }
    #pragma unroll
    for (int o = 16; o > 0; o >>= 1) {
        s  += __shfl_xor_sync(0xffffffffu, s,  o);
        sq += __shfl_xor_sync(0xffffffffu, sq, o);
    }
    if ((t & 31) == 0) { shs[t >> 5] = s; shq[t >> 5] = sq; }
    __syncthreads();
    if (t == 0) {
        float S = 0.f, Q = 0.f;
        #pragma unroll
        for (int i = 0; i < 8; i++) { S += shs[i]; Q += shq[i]; }
        float mean = S * (1.f / 16384.f);
        float var  = Q * (1.f / 16384.f) - mean * mean;
        shm[0] = mean;
        shm[1] = rsqrtf(var + 1e-6f);
    }
    __syncthreads();
    float mean = shm[0], rs = shm[1];
    int cl = t & 15;
    float scv = __ldg(&sc[g * 16 + cl]) * rs;
    float biv = __ldg(&bi[g * 16 + cl]);
    __half* op = outT + (size_t)b * HWW * CC + g * 16;
    #pragma unroll 4
    for (int j = 0; j < 64; j++) {
        int idx = t + 256 * j;
        int hw = idx >> 4;
        op[(size_t)hw * CC + cl] = __float2half_rn((xs[cl * 1026 + hw] - mean) * scv + biv);
    }
}

// ---------------------------------------------------------------------------
// In-place fp16 row softmax over 1024 (fp32 math)
// ---------------------------------------------------------------------------
__global__ void softmax_kernel(__half* __restrict__ Sh)
{
    __shared__ float sh[8];
    size_t row = blockIdx.x;
    __half2* p = (__half2*)(Sh + row * HWW);
    int t = threadIdx.x;

    __half2 h0 = p[2 * t], h1 = p[2 * t + 1];
    float2 a0 = __half22float2(h0), a1 = __half22float2(h1);
    float m = fmaxf(fmaxf(a0.x, a0.y), fmaxf(a1.x, a1.y));
    #pragma unroll
    for (int o = 16; o > 0; o >>= 1) m = fmaxf(m, __shfl_xor_sync(0xffffffffu, m, o));
    if ((t & 31) == 0) sh[t >> 5] = m;
    __syncthreads();
    float M = sh[0];
    #pragma unroll
    for (int i = 1; i < 8; i++) M = fmaxf(M, sh[i]);
    __syncthreads();

    a0.x = __expf(a0.x - M); a0.y = __expf(a0.y - M);
    a1.x = __expf(a1.x - M); a1.y = __expf(a1.y - M);
    float s = a0.x + a0.y + a1.x + a1.y;
    #pragma unroll
    for (int o = 16; o > 0; o >>= 1) s += __shfl_xor_sync(0xffffffffu, s, o);
    if ((t & 31) == 0) sh[t >> 5] = s;
    __syncthreads();
    float T = 0.f;
    #pragma unroll
    for (int i = 0; i < 8; i++) T += sh[i];
    float inv = 1.0f / T;

    p[2 * t + 0] = __floats2half2_rn(a0.x * inv, a0.y * inv);
    p[2 * t + 1] = __floats2half2_rn(a1.x * inv, a1.y * inv);
}

// ---------------------------------------------------------------------------
extern "C" void kernel_launch(void* const* d_in, const int* in_sizes, int n_in,
                              void* d_out, int out_size)
{
    const float* x   = (const float*)d_in[0];
    const float* y   = (const float*)d_in[1];
    const float* ns  = (const float*)d_in[2];
    const float* nb  = (const float*)d_in[3];
    const float* n1s = (const float*)d_in[4];
    const float* n1b = (const float*)d_in[5];
    const float* wq  = (const float*)d_in[6];
    const float* bq  = (const float*)d_in[7];
    const float* wk  = (const float*)d_in[8];
    const float* bk  = (const float*)d_in[9];
    const float* wv  = (const float*)d_in[10];
    const float* bv  = (const float*)d_in[11];
    const float* wp  = (const float*)d_in[12];
    const float* bp  = (const float*)d_in[13];
    float* out = (float*)d_out;

    __half *hxT, *hyT, *qT, *kT, *v2, *wh, *sh;
    cudaGetSymbolAddress((void**)&hxT, g_hxT);
    cudaGetSymbolAddress((void**)&hyT, g_hyT);
    cudaGetSymbolAddress((void**)&qT,  g_qT);
    cudaGetSymbolAddress((void**)&kT,  g_kT);
    cudaGetSymbolAddress((void**)&v2,  g_v2);
    cudaGetSymbolAddress((void**)&wh,  g_wh);
    cudaGetSymbolAddress((void**)&sh,  g_sh);
    __half* O = hxT;   // hxT dead after k,v GEMMs
    __half* whq = wh;
    __half* whk = wh + (size_t)CC * CC;
    __half* whv = wh + 2 * (size_t)CC * CC;
    __half* whp = wh + 3 * (size_t)CC * CC;

    const int SMEM_GEMM = 3 * 2 * 128 * 128;         // 98304 B
    const int SMEM_GN   = 16 * 1026 * sizeof(float); // 65664 B
    cudaFuncSetAttribute(mma_gemm<0>, cudaFuncAttributeMaxDynamicSharedMemorySize, SMEM_GEMM);
    cudaFuncSetAttribute(mma_gemm<1>, cudaFuncAttributeMaxDynamicSharedMemorySize, SMEM_GEMM);
    cudaFuncSetAttribute(mma_gemm<2>, cudaFuncAttributeMaxDynamicSharedMemorySize, SMEM_GEMM);
    cudaFuncSetAttribute(mma_gemm<3>, cudaFuncAttributeMaxDynamicSharedMemorySize, SMEM_GEMM);
    cudaFuncSetAttribute(mma_gemm<4>, cudaFuncAttributeMaxDynamicSharedMemorySize, SMEM_GEMM);
    cudaFuncSetAttribute(gn_t_kernel, cudaFuncAttributeMaxDynamicSharedMemorySize, SMEM_GN);

    const long AS = (long)CC * HWW;
    const long SS = (long)HWW * HWW;
    const float qkscale = 0.044194173824159216f;   // 512^-0.5

    // Weight conversion (1 MB total), single launch
    cvt_half4_kernel<<<dim3(256, 4), 256>>>(wq, wk, wv, wp, wh);

    // GroupNorm x and y, single launch (grid.y selects tensor)
    gn_t_kernel<<<dim3(BB * 32, 2), 256, SMEM_GN>>>(x, ns, nb, hxT, y, n1s, n1b, hyT);

    // q/k: D[hw, oc] = sum_c actT[hw,c] * W[oc,c] + b[oc]  (half out)
    dim3 gqkv(CC / 128, HWW / 128, BB);   // (4, 8, 16)
    mma_gemm<0><<<gqkv, 128, SMEM_GEMM>>>(hyT, whq, qT, bq, nullptr, 8, CC, CC, CC, AS, 0, AS, 0.f);
    mma_gemm<0><<<gqkv, 128, SMEM_GEMM>>>(hxT, whk, kT, bk, nullptr, 8, CC, CC, CC, AS, 0, AS, 0.f);
    // v: transposed half store -> v2[c][hw] (EPI=4, ldc=HWW)
    mma_gemm<4><<<gqkv, 128, SMEM_GEMM>>>(hxT, whv, v2, bv, nullptr, 8, CC, CC, HWW, AS, 0, AS, 0.f);

    // scores: Sh[i,j] = half(scale * sum_c qT[i,c] * kT[j,c])
    dim3 gqk(HWW / 128, HWW / 128, BB);   // (8, 8, 16)
    mma_gemm<1><<<gqk, 128, SMEM_GEMM>>>(qT, kT, sh, nullptr, nullptr, 8, CC, CC, HWW, AS, AS, SS, qkscale);

    softmax_kernel<<<BB * HWW, 256>>>(sh);

    // O[i, c] = sum_j probs[i,j] * v2[c,j]  (half out)
    dim3 gav(CC / 128, HWW / 128, BB);    // (4, 8, 16)
    mma_gemm<2><<<gav, 128, SMEM_GEMM>>>(sh, v2, O, nullptr, nullptr, 16, HWW, HWW, CC, SS, AS, AS, 0.f);

    // out[oc, hw] = sum_c wp[oc,c] * O[hw,c] + bp[oc] + x  (fp32 out)
    dim3 gproj(HWW / 128, CC / 128, BB);  // (8, 4, 16)
    mma_gemm<3><<<gproj, 128, SMEM_GEMM>>>(whp, O, out, bp, x, 8, CC, CC, HWW, 0, AS, AS, 0.f);
}

// round 14
// speedup vs baseline: 2.4934x; 1.0601x over previous
#include <cuda_runtime.h>
#include <cuda_fp16.h>
#include <cstdint>
#include <math.h>

#define BB   16
#define CC   512
#define HWW  1024
#define ABUF ((size_t)BB*CC*HWW)      // 8M elements

// Scratch (__device__ globals; no allocs allowed)
__device__ __half g_hxT[ABUF];   // normalized x, [b][hw][c] fp16; reused as O
__device__ __half g_hyT[ABUF];   // normalized y, [b][hw][c] fp16
__device__ __half g_qT [ABUF];   // [b][hw][c]
__device__ __half g_kT [ABUF];   // [b][hw][c]
__device__ __half g_v2 [ABUF];   // [b][c][hw]
__device__ __half g_wh [4*(size_t)CC*CC];       // fp16 weights: q,k,v,p
__device__ __half g_sh [(size_t)BB*HWW*HWW];    // fp16 scores -> probs (in-place)

__device__ __forceinline__ uint32_t smem_u32(const void* p) {
    uint32_t a;
    asm("{ .reg .u64 t; cvta.to.shared.u64 t, %1; cvt.u32.u64 %0, t; }" : "=r"(a) : "l"(p));
    return a;
}
#define CP_ASYNC16(sa, ga) \
    asm volatile("cp.async.cg.shared.global [%0], [%1], 16;" :: "r"(sa), "l"(ga) : "memory")
#define CP_COMMIT() asm volatile("cp.async.commit_group;" ::: "memory")
#define CP_WAIT1()  asm volatile("cp.async.wait_group 1;" ::: "memory")
#define CP_WAIT0()  asm volatile("cp.async.wait_group 0;" ::: "memory")

__device__ __forceinline__ void ldsm4(uint32_t& r0, uint32_t& r1, uint32_t& r2,
                                      uint32_t& r3, uint32_t addr) {
    asm volatile("ldmatrix.sync.aligned.m8n8.x4.shared.b16 {%0,%1,%2,%3}, [%4];"
                 : "=r"(r0), "=r"(r1), "=r"(r2), "=r"(r3) : "r"(addr));
}
#define HMMA16816(acc, a, b) \
    asm volatile( \
        "mma.sync.aligned.m16n8k16.row.col.f32.f16.f16.f32 " \
        "{%0,%1,%2,%3},{%4,%5,%6,%7},{%8,%9},{%0,%1,%2,%3};" \
        : "+f"(acc[0]), "+f"(acc[1]), "+f"(acc[2]), "+f"(acc[3]) \
        : "r"(a[0]), "r"(a[1]), "r"(a[2]), "r"(a[3]), "r"(b[0]), "r"(b[1]))

// ---------------------------------------------------------------------------
// Shared fp16 GEMM mainloop (macro-free via always_inline device func is
// awkward with lambdas; duplicated in mma_qkv). 128x128 tile, 3-stage
// cp.async, K-chunk 64 halves, XOR swizzle, ldmatrix.x4, reg-double-buffer.
// ---------------------------------------------------------------------------
#define GEMM_MAINLOOP(Ab, Bb, lda, ldb, NC)                                          \
    uint32_t smb = smem_u32(sm);                                                      \
    uint32_t rowA_off = (uint32_t)((wr * 64 + (lane & 15)) * 128);                    \
    uint32_t rowB_off = (uint32_t)((wc * 64 + lo7 + ((lane & 16) >> 1)) * 128);       \
    auto load = [&](int c, int s) {                                                   \
        int k0 = c * 64;                                                              \
        _Pragma("unroll")                                                             \
        for (int j = 0; j < 8; j++) {                                                 \
            int idx = t + 128 * j;                                                    \
            int r = idx >> 3, cq = idx & 7;                                           \
            int cs = cq ^ (r & 7);                                                    \
            const __half* ga = Ab + (size_t)(m0 + r) * lda + k0 + cq * 8;             \
            const __half* gb = Bb + (size_t)(n0 + r) * ldb + k0 + cq * 8;             \
            uint32_t so = (uint32_t)(s * STGB + r * 128 + cs * 16);                   \
            CP_ASYNC16(smb + so, ga);                                                 \
            CP_ASYNC16(smb + (uint32_t)TILEB + so, gb);                               \
        }                                                                             \
    };                                                                                \
    auto ldfrag = [&](uint32_t aBase, uint32_t bBase, int s16,                        \
                      uint32_t (&af)[4][4], uint32_t (&bf)[8][2]) {                   \
        uint32_t slA = (uint32_t)(((2 * s16 + hiA) ^ lo7) << 4);                      \
        uint32_t slB = (uint32_t)(((2 * s16 + hiB) ^ lo7) << 4);                      \
        uint32_t aAddr = aBase + rowA_off + slA;                                      \
        uint32_t bAddr = bBase + rowB_off + slB;                                      \
        _Pragma("unroll")                                                             \
        for (int i = 0; i < 4; i++)                                                   \
            ldsm4(af[i][0], af[i][1], af[i][2], af[i][3],                             \
                  aAddr + (uint32_t)(i * 16 * 128));                                  \
        _Pragma("unroll")                                                             \
        for (int p = 0; p < 4; p++)                                                   \
            ldsm4(bf[2 * p][0], bf[2 * p][1], bf[2 * p + 1][0], bf[2 * p + 1][1],     \
                  bAddr + (uint32_t)(p * 16 * 128));                                  \
    };                                                                                \
    load(0, 0); CP_COMMIT();                                                          \
    if (NC > 1) { load(1, 1); CP_COMMIT(); }                                          \
    uint32_t af[2][4][4], bf[2][8][2];                                                \
    for (int c = 0; c < NC; c++) {                                                    \
        if (c + 1 < NC) CP_WAIT1(); else CP_WAIT0();                                  \
        __syncthreads();                                                              \
        uint32_t aBase = smb + (uint32_t)((c % 3) * STGB);                            \
        uint32_t bBase = aBase + (uint32_t)TILEB;                                     \
        ldfrag(aBase, bBase, 0, af[0], bf[0]);                                        \
        if (c + 2 < NC) { load(c + 2, (c + 2) % 3); CP_COMMIT(); }                    \
        _Pragma("unroll")                                                             \
        for (int s16 = 0; s16 < 4; s16++) {                                           \
            if (s16 < 3) ldfrag(aBase, bBase, s16 + 1, af[(s16 + 1) & 1], bf[(s16 + 1) & 1]); \
            uint32_t (&a)[4][4] = af[s16 & 1];                                        \
            uint32_t (&b)[8][2] = bf[s16 & 1];                                        \
            _Pragma("unroll")                                                         \
            for (int i = 0; i < 4; i++)                                               \
                _Pragma("unroll")                                                     \
                for (int j = 0; j < 8; j++)                                           \
                    HMMA16816(acc[i][j], a[i], b[j]);                                 \
        }                                                                             \
    }

// ---------------------------------------------------------------------------
// Merged q/k/v kernel: grid (4, 8, 48); z = batch + 16*which (0=q,1=k,2=v).
// q/k: +bias[n] half store [hw][c]. v: +bias[n] transposed half store [c][hw].
// ---------------------------------------------------------------------------
__global__ __launch_bounds__(128, 2)
void mma_qkv(const __half* __restrict__ hyT, const __half* __restrict__ hxT,
             const __half* __restrict__ wh,
             __half* __restrict__ qT, __half* __restrict__ kT, __half* __restrict__ v2,
             const float* __restrict__ bq, const float* __restrict__ bk,
             const float* __restrict__ bv)
{
    extern __shared__ float sm[];
    const int TILEB = 128 * 128, STGB = 2 * TILEB;
    const long AS = (long)CC * HWW;

    int t = threadIdx.x, lane = t & 31, w = t >> 5;
    int wr = w & 1, wc = w >> 1;
    int g = lane >> 2, tg = lane & 3;
    int lo7 = lane & 7;
    int hiA = lane >> 4, hiB = (lane >> 3) & 1;
    int z = blockIdx.z;
    int bz = z & 15, which = z >> 4;
    int m0 = blockIdx.y * 128, n0 = blockIdx.x * 128;

    const __half* Ab = (which == 0 ? hyT : hxT) + (size_t)bz * AS;
    const __half* Bb = wh + (size_t)which * CC * CC;
    const float* bias = which == 0 ? bq : (which == 1 ? bk : bv);

    float acc[4][8][4];
    #pragma unroll
    for (int i = 0; i < 4; i++)
        #pragma unroll
        for (int j = 0; j < 8; j++)
            #pragma unroll
            for (int q = 0; q < 4; q++) acc[i][j][q] = 0.f;

    GEMM_MAINLOOP(Ab, Bb, CC, CC, 8)

    if (which < 2) {
        __half* Cb = (which ? kT : qT) + (size_t)bz * AS;
        int mrow = m0 + wr * 64, ncol = n0 + wc * 64;
        #pragma unroll
        for (int i = 0; i < 4; i++) {
            int r0 = mrow + i * 16 + g, r1 = r0 + 8;
            #pragma unroll
            for (int j = 0; j < 8; j++) {
                int cc = ncol + j * 8 + 2 * tg;
                float b0 = __ldg(&bias[cc]), b1 = __ldg(&bias[cc + 1]);
                *(__half2*)(Cb + (size_t)r0 * CC + cc) =
                    __floats2half2_rn(acc[i][j][0] + b0, acc[i][j][1] + b1);
                *(__half2*)(Cb + (size_t)r1 * CC + cc) =
                    __floats2half2_rn(acc[i][j][2] + b0, acc[i][j][3] + b1);
            }
        }
    } else {
        // transposed store via fp32 smem staging (pad 129)
        __half* Cb = v2 + (size_t)bz * AS;
        __syncthreads();
        #pragma unroll
        for (int i = 0; i < 4; i++) {
            int rl0 = wr * 64 + i * 16 + g, rl1 = rl0 + 8;
            #pragma unroll
            for (int j = 0; j < 8; j++) {
                int nl = wc * 64 + j * 8 + 2 * tg;
                float b0 = __ldg(&bias[n0 + nl]), b1 = __ldg(&bias[n0 + nl + 1]);
                sm[(nl + 0) * 129 + rl0] = acc[i][j][0] + b0;
                sm[(nl + 1) * 129 + rl0] = acc[i][j][1] + b1;
                sm[(nl + 0) * 129 + rl1] = acc[i][j][2] + b0;
                sm[(nl + 1) * 129 + rl1] = acc[i][j][3] + b1;
            }
        }
        __syncthreads();
        #pragma unroll 4
        for (int rr = 0; rr < 32; rr++) {
            int rloc = w * 32 + rr;
            __half* dst = Cb + (size_t)(n0 + rloc) * HWW + m0;
            const float* srcr = sm + rloc * 129;
            #pragma unroll
            for (int k2 = 0; k2 < 4; k2++)
                dst[lane + 32 * k2] = __float2half_rn(srcr[lane + 32 * k2]);
        }
    }
}

// ---------------------------------------------------------------------------
// Generic fp16 GEMM. EPI: 1=*scale->half | 2=none->half | 3=+bias[m]+resid->f32
// ---------------------------------------------------------------------------
template<int EPI>
__global__ __launch_bounds__(128, 2)
void mma_gemm(const __half* __restrict__ A, const __half* __restrict__ B,
              void* __restrict__ Cv, const float* __restrict__ bias,
              const float* __restrict__ resid,
              int NC, int lda, int ldb, int ldc,
              long aB, long bB, long cB, float scale)
{
    extern __shared__ float sm[];
    const int TILEB = 128 * 128, STGB = 2 * TILEB;

    int t = threadIdx.x, lane = t & 31, w = t >> 5;
    int wr = w & 1, wc = w >> 1;
    int g = lane >> 2, tg = lane & 3;
    int lo7 = lane & 7;
    int hiA = lane >> 4, hiB = (lane >> 3) & 1;
    int bz = blockIdx.z, m0 = blockIdx.y * 128, n0 = blockIdx.x * 128;
    const __half* Ab = A + (size_t)bz * aB;
    const __half* Bb = B + (size_t)bz * bB;

    float acc[4][8][4];
    #pragma unroll
    for (int i = 0; i < 4; i++)
        #pragma unroll
        for (int j = 0; j < 8; j++)
            #pragma unroll
            for (int q = 0; q < 4; q++) acc[i][j][q] = 0.f;

    GEMM_MAINLOOP(Ab, Bb, lda, ldb, NC)

    int mrow = m0 + wr * 64, ncol = n0 + wc * 64;
    #pragma unroll
    for (int i = 0; i < 4; i++) {
        int r0 = mrow + i * 16 + g, r1 = r0 + 8;
        float bm0 = 0.f, bm1 = 0.f;
        if (EPI == 3) { bm0 = __ldg(&bias[r0]); bm1 = __ldg(&bias[r1]); }
        #pragma unroll
        for (int j = 0; j < 8; j++) {
            int cc = ncol + j * 8 + 2 * tg;
            float2 v0 = make_float2(acc[i][j][0], acc[i][j][1]);
            float2 v1 = make_float2(acc[i][j][2], acc[i][j][3]);
            if (EPI == 1) {
                __half* Cb = (__half*)Cv + (size_t)bz * cB;
                *(__half2*)(Cb + (size_t)r0 * ldc + cc) = __floats2half2_rn(v0.x * scale, v0.y * scale);
                *(__half2*)(Cb + (size_t)r1 * ldc + cc) = __floats2half2_rn(v1.x * scale, v1.y * scale);
            } else if (EPI == 2) {
                __half* Cb = (__half*)Cv + (size_t)bz * cB;
                *(__half2*)(Cb + (size_t)r0 * ldc + cc) = __floats2half2_rn(v0.x, v0.y);
                *(__half2*)(Cb + (size_t)r1 * ldc + cc) = __floats2half2_rn(v1.x, v1.y);
            } else {
                float* Cb = (float*)Cv + (size_t)bz * cB;
                const float* Rb = resid + (size_t)bz * cB;
                float2 x0 = *(const float2*)(Rb + (size_t)r0 * ldc + cc);
                float2 x1 = *(const float2*)(Rb + (size_t)r1 * ldc + cc);
                v0.x += bm0 + x0.x; v0.y += bm0 + x0.y;
                v1.x += bm1 + x1.x; v1.y += bm1 + x1.y;
                *(float2*)(Cb + (size_t)r0 * ldc + cc) = v0;
                *(float2*)(Cb + (size_t)r1 * ldc + cc) = v1;
            }
        }
    }
}

// ---------------------------------------------------------------------------
// fp32 -> fp16 weight conversion, all 4 matrices in ONE launch (grid.y = mat)
// ---------------------------------------------------------------------------
__global__ void cvt_half4_kernel(const float* __restrict__ s0, const float* __restrict__ s1,
                                 const float* __restrict__ s2, const float* __restrict__ s3,
                                 __half* __restrict__ dst)
{
    const float* srcs[4] = {s0, s1, s2, s3};
    const float* src = srcs[blockIdx.y];
    int i = (blockIdx.x * blockDim.x + threadIdx.x) * 4;
    float4 v = *(const float4*)(src + i);
    __half2* d = (__half2*)(dst + (size_t)blockIdx.y * CC * CC + i);
    d[0] = __floats2half2_rn(v.x, v.y);
    d[1] = __floats2half2_rn(v.z, v.w);
}

// ---------------------------------------------------------------------------
// GroupNorm, both tensors in one launch (grid.y selects x/y), fp16 transposed
// output [b][hw][c]. One block per (b, group).
// ---------------------------------------------------------------------------
__global__ void gn_t_kernel(const float* __restrict__ x0, const float* __restrict__ sc0,
                            const float* __restrict__ bi0, __half* __restrict__ o0,
                            const float* __restrict__ x1, const float* __restrict__ sc1,
                            const float* __restrict__ bi1, __half* __restrict__ o1)
{
    extern __shared__ float xs[];      // 16 * 1026
    __shared__ float shs[8], shq[8], shm2[2];
    const float* x  = blockIdx.y ? x1  : x0;
    const float* sc = blockIdx.y ? sc1 : sc0;
    const float* bi = blockIdx.y ? bi1 : bi0;
    __half* outT    = blockIdx.y ? o1  : o0;
    int bg = blockIdx.x;
    int b = bg >> 5, g = bg & 31;
    const float* xp = x + ((size_t)b * CC + (size_t)g * 16) * HWW;
    int t = threadIdx.x;

    float s = 0.f, sq = 0.f;
    #pragma unroll 4
    for (int j = 0; j < 64; j++) {
        int idx = t + 256 * j;               // idx = c*1024 + hw
        float v = xp[idx];
        xs[(idx >> 10) * 1026 + (idx & 1023)] = v;
        s += v; sq += v * v;
    }
    #pragma unroll
    for (int o = 16; o > 0; o >>= 1) {
        s  += __shfl_xor_sync(0xffffffffu, s,  o);
        sq += __shfl_xor_sync(0xffffffffu, sq, o);
    }
    if ((t & 31) == 0) { shs[t >> 5] = s; shq[t >> 5] = sq; }
    __syncthreads();
    if (t == 0) {
        float S = 0.f, Q = 0.f;
        #pragma unroll
        for (int i = 0; i < 8; i++) { S += shs[i]; Q += shq[i]; }
        float mean = S * (1.f / 16384.f);
        float var  = Q * (1.f / 16384.f) - mean * mean;
        shm2[0] = mean;
        shm2[1] = rsqrtf(var + 1e-6f);
    }
    __syncthreads();
    float mean = shm2[0], rs = shm2[1];
    int cl = t & 15;
    float scv = __ldg(&sc[g * 16 + cl]) * rs;
    float biv = __ldg(&bi[g * 16 + cl]);
    __half* op = outT + (size_t)b * HWW * CC + g * 16;
    #pragma unroll 4
    for (int j = 0; j < 64; j++) {
        int idx = t + 256 * j;
        int hw = idx >> 4;
        op[(size_t)hw * CC + cl] = __float2half_rn((xs[cl * 1026 + hw] - mean) * scv + biv);
    }
}

// ---------------------------------------------------------------------------
// In-place fp16 row softmax: 2 rows per 256-thread block (warps 0-3 row 0,
// warps 4-7 row 1; shuffle reductions stay row-pure). uint4 (8-half) loads.
// ---------------------------------------------------------------------------
__global__ void softmax_kernel(__half* __restrict__ Sh)
{
    __shared__ float red[2][4];
    int t = threadIdx.x;
    int r = t >> 7, tt = t & 127;
    int w4 = (t >> 5) & 3;
    size_t row = (size_t)blockIdx.x * 2 + r;
    uint4* p = (uint4*)(Sh + row * HWW);

    uint4 u = p[tt];
    __half2 h[4];
    h[0] = *(__half2*)&u.x; h[1] = *(__half2*)&u.y;
    h[2] = *(__half2*)&u.z; h[3] = *(__half2*)&u.w;
    float2 a[4];
    #pragma unroll
    for (int i = 0; i < 4; i++) a[i] = __half22float2(h[i]);

    float m = a[0].x;
    #pragma unroll
    for (int i = 0; i < 4; i++) m = fmaxf(m, fmaxf(a[i].x, a[i].y));
    #pragma unroll
    for (int o = 16; o > 0; o >>= 1) m = fmaxf(m, __shfl_xor_sync(0xffffffffu, m, o));
    if ((t & 31) == 0) red[r][w4] = m;
    __syncthreads();
    float M = fmaxf(fmaxf(red[r][0], red[r][1]), fmaxf(red[r][2], red[r][3]));
    __syncthreads();

    float s = 0.f;
    #pragma unroll
    for (int i = 0; i < 4; i++) {
        a[i].x = __expf(a[i].x - M); a[i].y = __expf(a[i].y - M);
        s += a[i].x + a[i].y;
    }
    #pragma unroll
    for (int o = 16; o > 0; o >>= 1) s += __shfl_xor_sync(0xffffffffu, s, o);
    if ((t & 31) == 0) red[r][w4] = s;
    __syncthreads();
    float T = red[r][0] + red[r][1] + red[r][2] + red[r][3];
    float inv = 1.0f / T;

    __half2 o2[4];
    #pragma unroll
    for (int i = 0; i < 4; i++) o2[i] = __floats2half2_rn(a[i].x * inv, a[i].y * inv);
    uint4 ou;
    ou.x = *(uint32_t*)&o2[0]; ou.y = *(uint32_t*)&o2[1];
    ou.z = *(uint32_t*)&o2[2]; ou.w = *(uint32_t*)&o2[3];
    p[tt] = ou;
}

// ---------------------------------------------------------------------------
extern "C" void kernel_launch(void* const* d_in, const int* in_sizes, int n_in,
                              void* d_out, int out_size)
{
    const float* x   = (const float*)d_in[0];
    const float* y   = (const float*)d_in[1];
    const float* ns  = (const float*)d_in[2];
    const float* nb  = (const float*)d_in[3];
    const float* n1s = (const float*)d_in[4];
    const float* n1b = (const float*)d_in[5];
    const float* wq  = (const float*)d_in[6];
    const float* bq  = (const float*)d_in[7];
    const float* wk  = (const float*)d_in[8];
    const float* bk  = (const float*)d_in[9];
    const float* wv  = (const float*)d_in[10];
    const float* bv  = (const float*)d_in[11];
    const float* wp  = (const float*)d_in[12];
    const float* bp  = (const float*)d_in[13];
    float* out = (float*)d_out;

    __half *hxT, *hyT, *qT, *kT, *v2, *wh, *sh;
    cudaGetSymbolAddress((void**)&hxT, g_hxT);
    cudaGetSymbolAddress((void**)&hyT, g_hyT);
    cudaGetSymbolAddress((void**)&qT,  g_qT);
    cudaGetSymbolAddress((void**)&kT,  g_kT);
    cudaGetSymbolAddress((void**)&v2,  g_v2);
    cudaGetSymbolAddress((void**)&wh,  g_wh);
    cudaGetSymbolAddress((void**)&sh,  g_sh);
    __half* O = hxT;   // hxT dead after qkv kernel
    __half* whp = wh + 3 * (size_t)CC * CC;

    const int SMEM_GEMM = 3 * 2 * 128 * 128;         // 98304 B
    const int SMEM_GN   = 16 * 1026 * sizeof(float); // 65664 B
    cudaFuncSetAttribute(mma_qkv,     cudaFuncAttributeMaxDynamicSharedMemorySize, SMEM_GEMM);
    cudaFuncSetAttribute(mma_gemm<1>, cudaFuncAttributeMaxDynamicSharedMemorySize, SMEM_GEMM);
    cudaFuncSetAttribute(mma_gemm<2>, cudaFuncAttributeMaxDynamicSharedMemorySize, SMEM_GEMM);
    cudaFuncSetAttribute(mma_gemm<3>, cudaFuncAttributeMaxDynamicSharedMemorySize, SMEM_GEMM);
    cudaFuncSetAttribute(gn_t_kernel, cudaFuncAttributeMaxDynamicSharedMemorySize, SMEM_GN);

    const long AS = (long)CC * HWW;
    const long SS = (long)HWW * HWW;
    const float qkscale = 0.044194173824159216f;   // 512^-0.5

    // Weight conversion (1 MB total), single launch
    cvt_half4_kernel<<<dim3(256, 4), 256>>>(wq, wk, wv, wp, wh);

    // GroupNorm x and y, single launch (grid.y selects tensor)
    gn_t_kernel<<<dim3(BB * 32, 2), 256, SMEM_GN>>>(x, ns, nb, hxT, y, n1s, n1b, hyT);

    // q, k, v in ONE launch: grid.z = batch + 16*which
    mma_qkv<<<dim3(CC / 128, HWW / 128, 3 * BB), 128, SMEM_GEMM>>>(
        hyT, hxT, wh, qT, kT, v2, bq, bk, bv);

    // scores: Sh[i,j] = half(scale * sum_c qT[i,c] * kT[j,c])
    dim3 gqk(HWW / 128, HWW / 128, BB);   // (8, 8, 16)
    mma_gemm<1><<<gqk, 128, SMEM_GEMM>>>(qT, kT, sh, nullptr, nullptr, 8, CC, CC, HWW, AS, AS, SS, qkscale);

    softmax_kernel<<<BB * HWW / 2, 256>>>(sh);

    // O[i, c] = sum_j probs[i,j] * v2[c,j]  (half out)
    dim3 gav(CC / 128, HWW / 128, BB);    // (4, 8, 16)
    mma_gemm<2><<<gav, 128, SMEM_GEMM>>>(sh, v2, O, nullptr, nullptr, 16, HWW, HWW, CC, SS, AS, AS, 0.f);

    // out[oc, hw] = sum_c wp[oc,c] * O[hw,c] + bp[oc] + x  (fp32 out)
    dim3 gproj(HWW / 128, CC / 128, BB);  // (8, 4, 16)
    mma_gemm<3><<<gproj, 128, SMEM_GEMM>>>(whp, O, out, bp, x, 8, CC, CC, HWW, 0, AS, AS, 0.f);
}